// round 2
// baseline (speedup 1.0000x reference)
#include <cuda_runtime.h>
#include <cuda_bf16.h>
#include <mma.h>
#include <cfloat>
#include <math.h>

using namespace nvcuda;

#define SQ   1024
#define NH   128
#define DQ   192
#define DN   128
#define DR   64
#define DV   128
#define HID  7168
#define QLORA 1536
#define KVLORA 512
#define KVA_COLS 576   // 512 + 64
#define KVDIM 256      // D_NOPE + D_V per head

// ---------------- scratch (device globals; allocation-free rule) -------------
__device__ float g_qa[SQ * QLORA];                       //   6 MB
__device__ float g_kva[SQ * KVA_COLS];                   // 2.4 MB
__device__ float g_kpe[SQ * DR];                         // 256 KB
__device__ float g_q[SQ * NH * DQ];                      // 100 MB
__device__ float g_kv[SQ * NH * KVDIM];                  // 134 MB
__device__ float g_kfull[(long long)NH * SQ * DQ];       // 100 MB
__device__ float g_scores[(long long)NH * SQ * SQ];      // 537 MB
__device__ float g_attnout[SQ * NH * DV];                //  67 MB

// ---------------- 3xTF32 wmma GEMM (fp32-accurate) ---------------------------
// C[M,N] = A[M,K] @ B  (NT==false: B is [K,N] row-major; NT==true: B is [N,K] row-major)
// Each input split v = hi + lo (hi = tf32(v)); acc += hiA*hiB + loA*hiB + hiA*loB
constexpr int BM = 128, BN = 64, BK = 16, PAD = 4;

template <bool NT>
__global__ void __launch_bounds__(256)
gemm_3xtf32(const float* __restrict__ A, const float* __restrict__ B,
            float* __restrict__ C,
            int M, int N, int K, int lda, int ldb, int ldc,
            long long sA, long long sB, long long sC)
{
    const int b = blockIdx.z;
    A += (long long)b * sA;
    B += (long long)b * sB;
    C += (long long)b * sC;

    const int m0 = blockIdx.y * BM;
    const int n0 = blockIdx.x * BN;

    __shared__ float As_hi[BM][BK + PAD];
    __shared__ float As_lo[BM][BK + PAD];
    __shared__ float Bs_hi[BN][BK + PAD];
    __shared__ float Bs_lo[BN][BK + PAD];

    const int tid = threadIdx.x;
    const int wid = tid >> 5;
    const int wm  = (wid & 3) * 32;   // 4 warps over M
    const int wn  = (wid >> 2) * 32;  // 2 warps over N

    wmma::fragment<wmma::accumulator, 16, 16, 8, float> acc[2][2];
    #pragma unroll
    for (int i = 0; i < 2; i++)
        #pragma unroll
        for (int j = 0; j < 2; j++)
            wmma::fill_fragment(acc[i][j], 0.0f);

    for (int k0 = 0; k0 < K; k0 += BK) {
        // load A tile (BM x BK), split into hi/lo
        #pragma unroll
        for (int i = tid; i < BM * BK; i += 256) {
            int m = i / BK, k = i % BK;
            float v  = A[(long long)(m0 + m) * lda + (k0 + k)];
            float vh = wmma::__float_to_tf32(v);
            As_hi[m][k] = vh;
            As_lo[m][k] = wmma::__float_to_tf32(v - vh);
        }
        // load B tile into Bs[n][k], split into hi/lo
        #pragma unroll
        for (int i = tid; i < BN * BK; i += 256) {
            float v;
            int n, k;
            if (NT) {
                n = i / BK; k = i % BK;
                v = B[(long long)(n0 + n) * ldb + (k0 + k)];
            } else {
                k = i / BN; n = i % BN;
                v = B[(long long)(k0 + k) * ldb + (n0 + n)];
            }
            float vh = wmma::__float_to_tf32(v);
            Bs_hi[n][k] = vh;
            Bs_lo[n][k] = wmma::__float_to_tf32(v - vh);
        }
        __syncthreads();

        #pragma unroll
        for (int kk = 0; kk < BK; kk += 8) {
            wmma::fragment<wmma::matrix_a, 16, 16, 8, wmma::precision::tf32, wmma::row_major> ah[2], al[2];
            wmma::fragment<wmma::matrix_b, 16, 16, 8, wmma::precision::tf32, wmma::col_major> bh[2], bl[2];
            #pragma unroll
            for (int i = 0; i < 2; i++) {
                wmma::load_matrix_sync(ah[i], &As_hi[wm + 16 * i][kk], BK + PAD);
                wmma::load_matrix_sync(al[i], &As_lo[wm + 16 * i][kk], BK + PAD);
            }
            #pragma unroll
            for (int j = 0; j < 2; j++) {
                wmma::load_matrix_sync(bh[j], &Bs_hi[wn + 16 * j][kk], BK + PAD);
                wmma::load_matrix_sync(bl[j], &Bs_lo[wn + 16 * j][kk], BK + PAD);
            }
            #pragma unroll
            for (int i = 0; i < 2; i++)
                #pragma unroll
                for (int j = 0; j < 2; j++) {
                    wmma::mma_sync(acc[i][j], al[i], bh[j], acc[i][j]);  // lo*hi
                    wmma::mma_sync(acc[i][j], ah[i], bl[j], acc[i][j]);  // hi*lo
                    wmma::mma_sync(acc[i][j], ah[i], bh[j], acc[i][j]);  // hi*hi
                }
        }
        __syncthreads();
    }

    #pragma unroll
    for (int i = 0; i < 2; i++)
        #pragma unroll
        for (int j = 0; j < 2; j++)
            wmma::store_matrix_sync(
                &C[(long long)(m0 + wm + 16 * i) * ldc + (n0 + wn + 16 * j)],
                acc[i][j], ldc, wmma::mem_row_major);
}

// ---------------- rmsnorm (in-place, one block per row) ----------------------
__global__ void rmsnorm_kernel(float* __restrict__ x, const float* __restrict__ w,
                               int len, int stride)
{
    float* row = x + (long long)blockIdx.x * stride;
    __shared__ float red[256];
    int tid = threadIdx.x;
    float ss = 0.f;
    for (int j = tid; j < len; j += 256) { float v = row[j]; ss += v * v; }
    red[tid] = ss; __syncthreads();
    for (int s = 128; s > 0; s >>= 1) {
        if (tid < s) red[tid] += red[tid + s];
        __syncthreads();
    }
    float rr = rsqrtf(red[0] / (float)len + 1e-6f);
    for (int j = tid; j < len; j += 256) row[j] = row[j] * rr * w[j];
}

// ---------------- RoPE on q_pe (in-place; position == sequence index) --------
__global__ void rope_q_kernel(float* __restrict__ q)
{
    int idx = blockIdx.x * blockDim.x + threadIdx.x;
    if (idx >= SQ * NH * 32) return;
    int dp = idx & 31;
    int h  = (idx >> 5) & 127;
    int s  = idx >> 12;
    float p = (float)s;                       // position_ids == arange(S)
    float invf = __expf(-(float)dp * (logf(10000.f) / 32.f));
    float a = p * invf;
    float c, sn;
    sincosf(a, &sn, &c);
    float* base = q + (long long)s * (NH * DQ) + h * DQ + DN;
    float x1 = base[dp], x2 = base[dp + 32];
    base[dp]      = x1 * c - x2 * sn;
    base[dp + 32] = x2 * c + x1 * sn;
}

// ---------------- RoPE on k_pe (kva[:,512:576] -> g_kpe) ---------------------
__global__ void rope_kpe_kernel(const float* __restrict__ kva, float* __restrict__ kpe)
{
    int idx = blockIdx.x * blockDim.x + threadIdx.x;
    if (idx >= SQ * 32) return;
    int dp = idx & 31;
    int s  = idx >> 5;
    float p = (float)s;                       // position_ids == arange(S)
    float invf = __expf(-(float)dp * (logf(10000.f) / 32.f));
    float a = p * invf;
    float c, sn;
    sincosf(a, &sn, &c);
    const float* src = kva + (long long)s * KVA_COLS + KVLORA;
    float x1 = src[dp], x2 = src[dp + 32];
    kpe[s * DR + dp]      = x1 * c - x2 * sn;
    kpe[s * DR + dp + 32] = x2 * c + x1 * sn;
}

// ---------------- assemble K_full[h][s][0:192] --------------------------------
__global__ void assemble_k_kernel(const float* __restrict__ kv,
                                  const float* __restrict__ kpe,
                                  float* __restrict__ kfull)
{
    long long idx = (long long)blockIdx.x * blockDim.x + threadIdx.x;
    if (idx >= (long long)NH * SQ * DQ) return;
    int d = (int)(idx % DQ);
    int j = (int)((idx / DQ) % SQ);
    int h = (int)(idx / ((long long)DQ * SQ));
    float v;
    if (d < DN) v = kv[(long long)j * (NH * KVDIM) + h * KVDIM + d];
    else        v = kpe[j * DR + (d - DN)];
    kfull[idx] = v;
}

// ---------------- causal softmax (one block per (h, i) row) ------------------
__global__ void softmax_kernel(float* __restrict__ scores)
{
    int r = blockIdx.x;          // h*1024 + i
    int i = r & (SQ - 1);
    float* row = scores + (long long)r * SQ;
    const float scale = rsqrtf((float)DQ);
    __shared__ float red[256];
    int tid = threadIdx.x;

    float mx = -FLT_MAX;
    for (int j = tid; j <= i; j += 256) mx = fmaxf(mx, row[j] * scale);
    red[tid] = mx; __syncthreads();
    for (int s = 128; s > 0; s >>= 1) {
        if (tid < s) red[tid] = fmaxf(red[tid], red[tid + s]);
        __syncthreads();
    }
    mx = red[0];
    __syncthreads();

    float sum = 0.f;
    for (int j = tid; j <= i; j += 256) {
        float e = expf(row[j] * scale - mx);
        row[j] = e;
        sum += e;
    }
    red[tid] = sum; __syncthreads();
    for (int s = 128; s > 0; s >>= 1) {
        if (tid < s) red[tid] += red[tid + s];
        __syncthreads();
    }
    float inv = 1.f / red[0];

    for (int j = tid; j < SQ; j += 256)
        row[j] = (j <= i) ? row[j] * inv : 0.f;
}

// ---------------- host-side launch helpers -----------------------------------
static void launch_gemm(const float* A, const float* B, float* C,
                        int M, int N, int K, int lda, int ldb, int ldc,
                        long long sA, long long sB, long long sC,
                        int batch, bool nt)
{
    dim3 grid(N / BN, M / BM, batch), block(256);
    if (nt) gemm_3xtf32<true><<<grid, block>>>(A, B, C, M, N, K, lda, ldb, ldc, sA, sB, sC);
    else    gemm_3xtf32<false><<<grid, block>>>(A, B, C, M, N, K, lda, ldb, ldc, sA, sB, sC);
}

extern "C" void kernel_launch(void* const* d_in, const int* in_sizes, int n_in,
                              void* d_out, int out_size)
{
    const float* x     = (const float*)d_in[0];      // [1024, 7168]
    // d_in[1] = position_ids == arange(S); dtype ambiguous (int32 vs int64) -> unused
    const float* Wqa   = (const float*)d_in[2];      // [7168, 1536]
    const float* wqln  = (const float*)d_in[3];      // [1536]
    const float* Wqb   = (const float*)d_in[4];      // [1536, 24576]
    const float* Wkva  = (const float*)d_in[5];      // [7168, 576]
    const float* wkvln = (const float*)d_in[6];      // [512]
    const float* Wkvb  = (const float*)d_in[7];      // [512, 32768]
    const float* Wo    = (const float*)d_in[8];      // [16384, 7168]
    float*       out   = (float*)d_out;              // [1024, 7168]

    float *qa, *kva, *kpe, *q, *kv, *kfull, *scores, *attnout;
    cudaGetSymbolAddress((void**)&qa,      g_qa);
    cudaGetSymbolAddress((void**)&kva,     g_kva);
    cudaGetSymbolAddress((void**)&kpe,     g_kpe);
    cudaGetSymbolAddress((void**)&q,       g_q);
    cudaGetSymbolAddress((void**)&kv,      g_kv);
    cudaGetSymbolAddress((void**)&kfull,   g_kfull);
    cudaGetSymbolAddress((void**)&scores,  g_scores);
    cudaGetSymbolAddress((void**)&attnout, g_attnout);

    // 1) low-rank down-projections
    launch_gemm(x, Wqa,  qa,  SQ, QLORA,    HID, HID, QLORA,    QLORA,    0, 0, 0, 1, false);
    launch_gemm(x, Wkva, kva, SQ, KVA_COLS, HID, HID, KVA_COLS, KVA_COLS, 0, 0, 0, 1, false);

    // 2) rmsnorms (in-place)
    rmsnorm_kernel<<<SQ, 256>>>(qa,  wqln,  QLORA,  QLORA);
    rmsnorm_kernel<<<SQ, 256>>>(kva, wkvln, KVLORA, KVA_COLS);

    // 3) up-projections
    launch_gemm(qa,  Wqb,  q,  SQ, NH * DQ,    QLORA,  QLORA,    NH * DQ,    NH * DQ,    0, 0, 0, 1, false);
    launch_gemm(kva, Wkvb, kv, SQ, NH * KVDIM, KVLORA, KVA_COLS, NH * KVDIM, NH * KVDIM, 0, 0, 0, 1, false);

    // 4) RoPE + K assembly
    rope_q_kernel  <<<(SQ * NH * 32 + 255) / 256, 256>>>(q);
    rope_kpe_kernel<<<(SQ * 32 + 255) / 256, 256>>>(kva, kpe);
    assemble_k_kernel<<<(int)(((long long)NH * SQ * DQ + 255) / 256), 256>>>(kv, kpe, kfull);

    // 5) scores = Q @ K^T (batched over heads, NT)
    launch_gemm(q, kfull, scores, SQ, SQ, DQ,
                NH * DQ, DQ, SQ,
                DQ, (long long)SQ * DQ, (long long)SQ * SQ, NH, true);

    // 6) causal softmax
    softmax_kernel<<<NH * SQ, 256>>>(scores);

    // 7) out_h = P @ V (batched over heads, NN); V = kv[:, h*256+128 : h*256+256]
    launch_gemm(scores, kv + DN, attnout, SQ, DV, SQ,
                SQ, NH * KVDIM, NH * DV,
                (long long)SQ * SQ, KVDIM, DV, NH, false);

    // 8) output projection
    launch_gemm(attnout, Wo, out, SQ, HID, NH * DV,
                NH * DV, HID, HID, 0, 0, 0, 1, false);
}

// round 4
// speedup vs baseline: 4.4478x; 4.4478x over previous
#include <cuda_runtime.h>
#include <cuda_bf16.h>
#include <mma.h>
#include <cfloat>
#include <cstdint>
#include <math.h>
#include <type_traits>

using namespace nvcuda;
typedef __nv_bfloat16 bf16;

#define SQ   1024
#define NH   128
#define DQ   192
#define DN   128
#define DR   64
#define DV   128
#define HID  7168
#define QLORA 1536
#define KVLORA 512
#define KVA_COLS 576
#define KVDIM 256

// ---------------- scratch (device globals; allocation-free rule) -------------
// fp32 intermediates
__device__ float g_qa[SQ * QLORA];
__device__ float g_kva[SQ * KVA_COLS];
__device__ float g_kpe[SQ * DR];
__device__ float g_q[SQ * NH * DQ];
__device__ float g_kv[SQ * NH * KVDIM];
__device__ float g_attnout[SQ * NH * DV];
__device__ float g_scores[(long long)NH * SQ * SQ];

// bf16 hi/lo split operands
__device__ bf16 g_xh[SQ * HID],            g_xl[SQ * HID];
__device__ bf16 g_Wqa_h[HID * QLORA],      g_Wqa_l[HID * QLORA];
__device__ bf16 g_Wqb_h[QLORA * NH * DQ],  g_Wqb_l[QLORA * NH * DQ];
__device__ bf16 g_Wkva_h[HID * KVA_COLS],  g_Wkva_l[HID * KVA_COLS];
__device__ bf16 g_Wkvb_h[KVLORA * NH * KVDIM], g_Wkvb_l[KVLORA * NH * KVDIM];
__device__ bf16 g_Wo_h[NH * DV * HID],     g_Wo_l[NH * DV * HID];
__device__ bf16 g_qah[SQ * QLORA],         g_qal[SQ * QLORA];
__device__ bf16 g_kvah[SQ * KVA_COLS],     g_kval[SQ * KVA_COLS];
__device__ bf16 g_qh[SQ * NH * DQ],        g_ql[SQ * NH * DQ];
__device__ bf16 g_kh[(long long)NH * SQ * DQ], g_kl[(long long)NH * SQ * DQ];
__device__ bf16 g_kvh[SQ * NH * KVDIM],    g_kvl[SQ * NH * KVDIM];
__device__ bf16 g_Ph[(long long)NH * SQ * SQ], g_Pl[(long long)NH * SQ * SQ];
__device__ bf16 g_aoh[SQ * NH * DV],       g_aol[SQ * NH * DV];

// ---------------- helpers -----------------------------------------------------
__device__ __forceinline__ void cp_async16(bf16* smem_dst, const bf16* gsrc) {
    unsigned int saddr = (unsigned int)__cvta_generic_to_shared(smem_dst);
    asm volatile("cp.async.cg.shared.global [%0], [%1], 16;\n" :: "r"(saddr), "l"(gsrc));
}
#define CP_COMMIT() asm volatile("cp.async.commit_group;\n")
#define CP_WAIT1()  asm volatile("cp.async.wait_group 1;\n")

// ---------------- split fp32 -> (bf16 hi, bf16 lo) ----------------------------
__global__ void split_kernel(const float4* __restrict__ src,
                             __nv_bfloat162* __restrict__ h,
                             __nv_bfloat162* __restrict__ l, int n4)
{
    int i = blockIdx.x * blockDim.x + threadIdx.x;
    if (i >= n4) return;
    float4 v = src[i];
    bf16 h0 = __float2bfloat16(v.x), h1 = __float2bfloat16(v.y);
    bf16 h2 = __float2bfloat16(v.z), h3 = __float2bfloat16(v.w);
    bf16 l0 = __float2bfloat16(v.x - __bfloat162float(h0));
    bf16 l1 = __float2bfloat16(v.y - __bfloat162float(h1));
    bf16 l2 = __float2bfloat16(v.z - __bfloat162float(h2));
    bf16 l3 = __float2bfloat16(v.w - __bfloat162float(h3));
    h[2*i]   = __nv_bfloat162(h0, h1);
    h[2*i+1] = __nv_bfloat162(h2, h3);
    l[2*i]   = __nv_bfloat162(l0, l1);
    l[2*i+1] = __nv_bfloat162(l2, l3);
}

// ---------------- 3xBF16 GEMM with cp.async double buffering ------------------
// C[M,N] = A@B; A hi/lo bf16 row-major [M,K]; B hi/lo bf16:
//   NT=false: [K,N] row-major ; NT=true: [N,K] row-major (B transposed)
constexpr int BM = 128, BK = 32;

template <int BN_, bool NT, bool CSKIP, bool KLIM>
__global__ void __launch_bounds__(256)
gemm3(const bf16* __restrict__ Ah, const bf16* __restrict__ Al,
      const bf16* __restrict__ Bh, const bf16* __restrict__ Bl,
      float* __restrict__ C, int M, int N, int K,
      int lda, int ldb, int ldc, long long sA, long long sB, long long sC)
{
    constexpr int LDA_S = BK + 8;                 // 40
    constexpr int LDB_S = NT ? (BK + 8) : (BN_ + 8);
    constexpr int B_ROWS = NT ? BN_ : BK;
    constexpr int A_TILE = BM * LDA_S;
    constexpr int B_TILE = B_ROWS * LDB_S;
    constexpr int STAGE  = 2 * A_TILE + 2 * B_TILE;
    constexpr int WN = BN_ / 2;                   // warp N extent
    constexpr int NF = WN / 16;                   // N frags per warp
    using BLay = typename std::conditional<NT, wmma::col_major, wmma::row_major>::type;

    const int b = blockIdx.z;
    Ah += b * sA; Al += b * sA;
    Bh += b * sB; Bl += b * sB;
    C  += b * sC;

    const int m0 = blockIdx.y * BM;
    const int n0 = blockIdx.x * BN_;
    if (CSKIP && n0 >= m0 + BM) return;
    const int Kend = KLIM ? (m0 + BM < K ? m0 + BM : K) : K;

    extern __shared__ bf16 dynsmem[];

    const int tid = threadIdx.x;
    const int wid = tid >> 5;
    const int wm  = (wid & 3) * 32;
    const int wn  = (wid >> 2) * WN;

    auto load_stage = [&](int st, int k0) {
        bf16* base = dynsmem + st * STAGE;
        bf16* sAh_ = base;
        bf16* sAl_ = base + A_TILE;
        bf16* sBh_ = base + 2 * A_TILE;
        bf16* sBl_ = base + 2 * A_TILE + B_TILE;
        #pragma unroll
        for (int c = tid; c < BM * 4; c += 256) {
            int m = c >> 2, k8 = (c & 3) << 3;
            long long g = (long long)(m0 + m) * lda + k0 + k8;
            cp_async16(sAh_ + m * LDA_S + k8, Ah + g);
            cp_async16(sAl_ + m * LDA_S + k8, Al + g);
        }
        if (NT) {
            #pragma unroll
            for (int c = tid; c < BN_ * 4; c += 256) {
                int n = c >> 2, k8 = (c & 3) << 3;
                long long g = (long long)(n0 + n) * ldb + k0 + k8;
                cp_async16(sBh_ + n * LDB_S + k8, Bh + g);
                cp_async16(sBl_ + n * LDB_S + k8, Bl + g);
            }
        } else {
            constexpr int CPR = BN_ / 8;
            #pragma unroll
            for (int c = tid; c < BK * CPR; c += 256) {
                int k = c / CPR, n8 = (c % CPR) * 8;
                long long g = (long long)(k0 + k) * ldb + n0 + n8;
                cp_async16(sBh_ + k * LDB_S + n8, Bh + g);
                cp_async16(sBl_ + k * LDB_S + n8, Bl + g);
            }
        }
    };

    wmma::fragment<wmma::accumulator, 16, 16, 16, float> acc[2][NF];
    #pragma unroll
    for (int i = 0; i < 2; i++)
        #pragma unroll
        for (int j = 0; j < NF; j++)
            wmma::fill_fragment(acc[i][j], 0.0f);

    const int nK = Kend / BK;
    load_stage(0, 0);
    CP_COMMIT();

    for (int kt = 0; kt < nK; kt++) {
        if (kt + 1 < nK) load_stage((kt + 1) & 1, (kt + 1) * BK);
        CP_COMMIT();
        CP_WAIT1();
        __syncthreads();

        const bf16* base = dynsmem + (kt & 1) * STAGE;
        const bf16* cAh = base;
        const bf16* cAl = base + A_TILE;
        const bf16* cBh = base + 2 * A_TILE;
        const bf16* cBl = base + 2 * A_TILE + B_TILE;

        #pragma unroll
        for (int kk = 0; kk < BK; kk += 16) {
            wmma::fragment<wmma::matrix_a, 16, 16, 16, bf16, wmma::row_major> ah[2], al[2];
            #pragma unroll
            for (int i = 0; i < 2; i++) {
                wmma::load_matrix_sync(ah[i], cAh + (wm + 16 * i) * LDA_S + kk, LDA_S);
                wmma::load_matrix_sync(al[i], cAl + (wm + 16 * i) * LDA_S + kk, LDA_S);
            }
            wmma::fragment<wmma::matrix_b, 16, 16, 16, bf16, BLay> bh[NF], bl[NF];
            #pragma unroll
            for (int j = 0; j < NF; j++) {
                if (NT) {
                    wmma::load_matrix_sync(bh[j], cBh + (wn + 16 * j) * LDB_S + kk, LDB_S);
                    wmma::load_matrix_sync(bl[j], cBl + (wn + 16 * j) * LDB_S + kk, LDB_S);
                } else {
                    wmma::load_matrix_sync(bh[j], cBh + kk * LDB_S + wn + 16 * j, LDB_S);
                    wmma::load_matrix_sync(bl[j], cBl + kk * LDB_S + wn + 16 * j, LDB_S);
                }
            }
            #pragma unroll
            for (int i = 0; i < 2; i++)
                #pragma unroll
                for (int j = 0; j < NF; j++) {
                    wmma::mma_sync(acc[i][j], ah[i], bh[j], acc[i][j]);
                    wmma::mma_sync(acc[i][j], ah[i], bl[j], acc[i][j]);
                    wmma::mma_sync(acc[i][j], al[i], bh[j], acc[i][j]);
                }
        }
        __syncthreads();
    }

    #pragma unroll
    for (int i = 0; i < 2; i++)
        #pragma unroll
        for (int j = 0; j < NF; j++)
            wmma::store_matrix_sync(
                &C[(long long)(m0 + wm + 16 * i) * ldc + (n0 + wn + 16 * j)],
                acc[i][j], ldc, wmma::mem_row_major);
}

template <int BN_, bool NT, bool CSKIP, bool KLIM>
static void run_gemm(const bf16* Ah, const bf16* Al, const bf16* Bh, const bf16* Bl,
                     float* C, int M, int N, int K, int lda, int ldb, int ldc,
                     long long sA, long long sB, long long sC, int batch)
{
    constexpr int LDA_S = BK + 8;
    constexpr int LDB_S = NT ? (BK + 8) : (BN_ + 8);
    constexpr int B_ROWS = NT ? BN_ : BK;
    size_t smem = (size_t)2 * (2 * BM * LDA_S + 2 * B_ROWS * LDB_S) * sizeof(bf16);
    cudaFuncSetAttribute(gemm3<BN_, NT, CSKIP, KLIM>,
                         cudaFuncAttributeMaxDynamicSharedMemorySize, (int)smem);
    dim3 grid(N / BN_, M / BM, batch);
    gemm3<BN_, NT, CSKIP, KLIM><<<grid, 256, smem>>>(Ah, Al, Bh, Bl, C,
                                                     M, N, K, lda, ldb, ldc, sA, sB, sC);
}

// ---------------- rmsnorm (in-place) -------------------------------------------
__global__ void rmsnorm_kernel(float* __restrict__ x, const float* __restrict__ w,
                               int len, int stride)
{
    float* row = x + (long long)blockIdx.x * stride;
    __shared__ float red[256];
    int tid = threadIdx.x;
    float ss = 0.f;
    for (int j = tid; j < len; j += 256) { float v = row[j]; ss += v * v; }
    red[tid] = ss; __syncthreads();
    for (int s = 128; s > 0; s >>= 1) {
        if (tid < s) red[tid] += red[tid + s];
        __syncthreads();
    }
    float rr = rsqrtf(red[0] / (float)len + 1e-6f);
    for (int j = tid; j < len; j += 256) row[j] = row[j] * rr * w[j];
}

// ---------------- RoPE on q_pe (fp32 in place) ----------------------------------
__global__ void rope_q_kernel(float* __restrict__ q)
{
    int idx = blockIdx.x * blockDim.x + threadIdx.x;
    if (idx >= SQ * NH * 32) return;
    int dp = idx & 31;
    int h  = (idx >> 5) & 127;
    int s  = idx >> 12;
    float a = (float)s * __expf(-(float)dp * (logf(10000.f) / 32.f));
    float c, sn;
    sincosf(a, &sn, &c);
    float* base = q + (long long)s * (NH * DQ) + h * DQ + DN;
    float x1 = base[dp], x2 = base[dp + 32];
    base[dp]      = x1 * c - x2 * sn;
    base[dp + 32] = x2 * c + x1 * sn;
}

__global__ void rope_kpe_kernel(const float* __restrict__ kva, float* __restrict__ kpe)
{
    int idx = blockIdx.x * blockDim.x + threadIdx.x;
    if (idx >= SQ * 32) return;
    int dp = idx & 31;
    int s  = idx >> 5;
    float a = (float)s * __expf(-(float)dp * (logf(10000.f) / 32.f));
    float c, sn;
    sincosf(a, &sn, &c);
    const float* src = kva + (long long)s * KVA_COLS + KVLORA;
    float x1 = src[dp], x2 = src[dp + 32];
    kpe[s * DR + dp]      = x1 * c - x2 * sn;
    kpe[s * DR + dp + 32] = x2 * c + x1 * sn;
}

// ---------------- assemble K_full -> bf16 hi/lo ---------------------------------
__global__ void assemble_k_split_kernel(const float* __restrict__ kv,
                                        const float* __restrict__ kpe,
                                        bf16* __restrict__ kh, bf16* __restrict__ kl)
{
    long long idx = (long long)blockIdx.x * blockDim.x + threadIdx.x;
    if (idx >= (long long)NH * SQ * DQ) return;
    int d = (int)(idx % DQ);
    int j = (int)((idx / DQ) % SQ);
    int h = (int)(idx / ((long long)DQ * SQ));
    float v;
    if (d < DN) v = kv[(long long)j * (NH * KVDIM) + h * KVDIM + d];
    else        v = kpe[j * DR + (d - DN)];
    bf16 hi = __float2bfloat16(v);
    kh[idx] = hi;
    kl[idx] = __float2bfloat16(v - __bfloat162float(hi));
}

// ---------------- causal softmax + split to bf16 hi/lo --------------------------
__global__ void softmax_split_kernel(const float* __restrict__ scores,
                                     bf16* __restrict__ Ph, bf16* __restrict__ Pl)
{
    int r = blockIdx.x;                 // h*1024 + i
    int i = r & (SQ - 1);
    const float* row = scores + (long long)r * SQ;
    bf16* ph = Ph + (long long)r * SQ;
    bf16* pl = Pl + (long long)r * SQ;
    const float scale = 0.07216878365f; // 1/sqrt(192)
    int tid = threadIdx.x;
    int lane = tid & 31, warp = tid >> 5;
    __shared__ float redm[8], reds[8];

    float v[4];
    #pragma unroll
    for (int t = 0; t < 4; t++) {
        int j = tid + t * 256;
        v[t] = (j <= i) ? row[j] * scale : -FLT_MAX;
    }
    float mx = fmaxf(fmaxf(v[0], v[1]), fmaxf(v[2], v[3]));
    #pragma unroll
    for (int o = 16; o > 0; o >>= 1) mx = fmaxf(mx, __shfl_xor_sync(~0u, mx, o));
    if (lane == 0) redm[warp] = mx;
    __syncthreads();
    mx = redm[0];
    #pragma unroll
    for (int w = 1; w < 8; w++) mx = fmaxf(mx, redm[w]);

    float e[4];
    float sum = 0.f;
    #pragma unroll
    for (int t = 0; t < 4; t++) {
        int j = tid + t * 256;
        e[t] = (j <= i) ? __expf(v[t] - mx) : 0.f;
        sum += e[t];
    }
    #pragma unroll
    for (int o = 16; o > 0; o >>= 1) sum += __shfl_xor_sync(~0u, sum, o);
    if (lane == 0) reds[warp] = sum;
    __syncthreads();
    sum = 0.f;
    #pragma unroll
    for (int w = 0; w < 8; w++) sum += reds[w];
    float inv = 1.f / sum;

    #pragma unroll
    for (int t = 0; t < 4; t++) {
        int j = tid + t * 256;
        float p = e[t] * inv;
        bf16 hi = __float2bfloat16(p);
        ph[j] = hi;
        pl[j] = __float2bfloat16(p - __bfloat162float(hi));
    }
}

// ---------------- host side -----------------------------------------------------
static void split(const float* src, bf16* h, bf16* l, long long n)
{
    int n4 = (int)(n / 4);
    split_kernel<<<(n4 + 255) / 256, 256>>>((const float4*)src,
                                            (__nv_bfloat162*)h, (__nv_bfloat162*)l, n4);
}

extern "C" void kernel_launch(void* const* d_in, const int* in_sizes, int n_in,
                              void* d_out, int out_size)
{
    const float* x     = (const float*)d_in[0];
    const float* Wqa   = (const float*)d_in[2];
    const float* wqln  = (const float*)d_in[3];
    const float* Wqb   = (const float*)d_in[4];
    const float* Wkva  = (const float*)d_in[5];
    const float* wkvln = (const float*)d_in[6];
    const float* Wkvb  = (const float*)d_in[7];
    const float* Wo    = (const float*)d_in[8];
    float*       out   = (float*)d_out;

    float *qa, *kva, *kpe, *q, *kv, *scores, *attnout;
    cudaGetSymbolAddress((void**)&qa,      g_qa);
    cudaGetSymbolAddress((void**)&kva,     g_kva);
    cudaGetSymbolAddress((void**)&kpe,     g_kpe);
    cudaGetSymbolAddress((void**)&q,       g_q);
    cudaGetSymbolAddress((void**)&kv,      g_kv);
    cudaGetSymbolAddress((void**)&scores,  g_scores);
    cudaGetSymbolAddress((void**)&attnout, g_attnout);

    bf16 *xh,*xl,*Wqah,*Wqal,*Wqbh,*Wqbl,*Wkvah,*Wkval,*Wkvbh,*Wkvbl,*Woh,*Wol;
    bf16 *qah,*qal,*kvah,*kval,*qh,*ql,*kh,*kl,*kvh,*kvl,*Phb,*Plb,*aoh,*aol;
    cudaGetSymbolAddress((void**)&xh,    g_xh);    cudaGetSymbolAddress((void**)&xl,    g_xl);
    cudaGetSymbolAddress((void**)&Wqah,  g_Wqa_h); cudaGetSymbolAddress((void**)&Wqal,  g_Wqa_l);
    cudaGetSymbolAddress((void**)&Wqbh,  g_Wqb_h); cudaGetSymbolAddress((void**)&Wqbl,  g_Wqb_l);
    cudaGetSymbolAddress((void**)&Wkvah, g_Wkva_h);cudaGetSymbolAddress((void**)&Wkval, g_Wkva_l);
    cudaGetSymbolAddress((void**)&Wkvbh, g_Wkvb_h);cudaGetSymbolAddress((void**)&Wkvbl, g_Wkvb_l);
    cudaGetSymbolAddress((void**)&Woh,   g_Wo_h);  cudaGetSymbolAddress((void**)&Wol,   g_Wo_l);
    cudaGetSymbolAddress((void**)&qah,   g_qah);   cudaGetSymbolAddress((void**)&qal,   g_qal);
    cudaGetSymbolAddress((void**)&kvah,  g_kvah);  cudaGetSymbolAddress((void**)&kval,  g_kval);
    cudaGetSymbolAddress((void**)&qh,    g_qh);    cudaGetSymbolAddress((void**)&ql,    g_ql);
    cudaGetSymbolAddress((void**)&kh,    g_kh);    cudaGetSymbolAddress((void**)&kl,    g_kl);
    cudaGetSymbolAddress((void**)&kvh,   g_kvh);   cudaGetSymbolAddress((void**)&kvl,   g_kvl);
    cudaGetSymbolAddress((void**)&Phb,   g_Ph);    cudaGetSymbolAddress((void**)&Plb,   g_Pl);
    cudaGetSymbolAddress((void**)&aoh,   g_aoh);   cudaGetSymbolAddress((void**)&aol,   g_aol);

    // 0) split inputs / weights into bf16 hi/lo
    split(x,    xh,    xl,    (long long)SQ * HID);
    split(Wqa,  Wqah,  Wqal,  (long long)HID * QLORA);
    split(Wqb,  Wqbh,  Wqbl,  (long long)QLORA * NH * DQ);
    split(Wkva, Wkvah, Wkval, (long long)HID * KVA_COLS);
    split(Wkvb, Wkvbh, Wkvbl, (long long)KVLORA * NH * KVDIM);
    split(Wo,   Woh,   Wol,   (long long)NH * DV * HID);

    // 1) down-projections
    run_gemm<128,false,false,false>(xh, xl, Wqah, Wqal, qa,
        SQ, QLORA, HID, HID, QLORA, QLORA, 0, 0, 0, 1);
    run_gemm<64,false,false,false>(xh, xl, Wkvah, Wkval, kva,
        SQ, KVA_COLS, HID, HID, KVA_COLS, KVA_COLS, 0, 0, 0, 1);

    // 2) rmsnorms
    rmsnorm_kernel<<<SQ, 256>>>(qa,  wqln,  QLORA,  QLORA);
    rmsnorm_kernel<<<SQ, 256>>>(kva, wkvln, KVLORA, KVA_COLS);

    // 3) split normalized activations, up-projections
    split(qa,  qah,  qal,  (long long)SQ * QLORA);
    split(kva, kvah, kval, (long long)SQ * KVA_COLS);
    run_gemm<128,false,false,false>(qah, qal, Wqbh, Wqbl, q,
        SQ, NH * DQ, QLORA, QLORA, NH * DQ, NH * DQ, 0, 0, 0, 1);
    run_gemm<128,false,false,false>(kvah, kval, Wkvbh, Wkvbl, kv,
        SQ, NH * KVDIM, KVLORA, KVA_COLS, NH * KVDIM, NH * KVDIM, 0, 0, 0, 1);

    // 4) RoPE, K assembly, operand splits
    rope_q_kernel  <<<(SQ * NH * 32 + 255) / 256, 256>>>(q);
    rope_kpe_kernel<<<(SQ * 32 + 255) / 256, 256>>>(kva, kpe);
    split(q, qh, ql, (long long)SQ * NH * DQ);
    assemble_k_split_kernel<<<(int)(((long long)NH * SQ * DQ + 255) / 256), 256>>>(kv, kpe, kh, kl);
    split(kv, kvh, kvl, (long long)SQ * NH * KVDIM);

    // 5) scores = Q @ K^T (batched, NT, causal tile-skip)
    run_gemm<128,true,true,false>(qh, ql, kh, kl, scores,
        SQ, SQ, DQ, NH * DQ, DQ, SQ,
        DQ, (long long)SQ * DQ, (long long)SQ * SQ, NH);

    // 6) causal softmax + split
    softmax_split_kernel<<<NH * SQ, 256>>>(scores, Phb, Plb);

    // 7) out_h = P @ V (batched, k-limited by causality)
    run_gemm<128,false,false,true>(Phb, Plb, kvh + DN, kvl + DN, attnout,
        SQ, DV, SQ, SQ, NH * KVDIM, NH * DV,
        (long long)SQ * SQ, KVDIM, DV, NH);

    // 8) output projection
    split(attnout, aoh, aol, (long long)SQ * NH * DV);
    run_gemm<128,false,false,false>(aoh, aol, Woh, Wol, out,
        SQ, HID, NH * DV, NH * DV, HID, HID, 0, 0, 0, 1);
}

// round 7
// speedup vs baseline: 6.8159x; 1.5324x over previous
#include <cuda_runtime.h>
#include <cuda_fp16.h>
#include <mma.h>
#include <cfloat>
#include <cstdint>
#include <math.h>

using namespace nvcuda;
typedef __half h16;

#define SQ   1024
#define NH   128
#define DQ   192
#define DN   128
#define DR   64
#define DV   128
#define HID  7168
#define QLORA 1536
#define KVLORA 512
#define KVAP 640          // padded kv_a width (576 -> 640)

// ---------------- scratch (device globals; allocation-free rule) -------------
__device__ float g_qa[SQ * QLORA];
__device__ float g_kva[SQ * KVAP];
__device__ float g_kpe[SQ * DR];
__device__ float g_q[SQ * NH * DQ];
__device__ float g_kv[SQ * NH * 256];
__device__ float g_attnout[SQ * NH * DV];
__device__ float g_scores[(long long)NH * SQ * SQ];

// fp16 hi/lo activations
__device__ h16 g_xh[SQ * HID],        g_xl[SQ * HID];
__device__ h16 g_qah[SQ * QLORA],     g_qal[SQ * QLORA];
__device__ h16 g_kvah[SQ * KVAP],     g_kval[SQ * KVAP];
__device__ h16 g_qh[SQ * NH * DQ],    g_ql[SQ * NH * DQ];
__device__ h16 g_kh[(long long)NH * SQ * DQ], g_kl[(long long)NH * SQ * DQ];
__device__ h16 g_Ph[(long long)NH * SQ * SQ], g_Pl[(long long)NH * SQ * SQ];
__device__ h16 g_aoh[SQ * NH * DV],   g_aol[SQ * NH * DV];

// fp16 transposed weights ([N][K] K-major). 3-term GEMMs keep lo; 2-term hi only.
__device__ h16 g_Wqa_t_h[QLORA * HID],  g_Wqa_t_l[QLORA * HID];
__device__ h16 g_Wkva_t_h[KVAP * HID],  g_Wkva_t_l[KVAP * HID];
__device__ h16 g_Wqb_t_h[NH * DQ * QLORA];
__device__ h16 g_Wkvb_t_h[NH * 256 * KVLORA];
__device__ h16 g_Wo_t_h[(long long)HID * NH * DV];
__device__ h16 g_Vt_h[(long long)NH * DV * SQ], g_Vt_l[(long long)NH * DV * SQ];

// ---------------- helpers -----------------------------------------------------
__device__ __forceinline__ void cp16(const h16* smem_dst, const h16* gsrc) {
    unsigned int saddr = (unsigned int)__cvta_generic_to_shared(smem_dst);
    asm volatile("cp.async.cg.shared.global [%0], [%1], 16;\n" :: "r"(saddr), "l"(gsrc));
}

// ---------------- 2/3-term fp16 GEMM, 3-stage cp.async ------------------------
// C[M,N] = A[M,K] @ B[N,K]^T   (A,B K-major fp16 hi/lo; batch via blockIdx.z)
// TERMS==3: C = Ah*Bh + Al*Bh + Ah*Bl ; TERMS==2: C = Ah*Bh + Al*Bh (Bl unused)
template <int TERMS, bool CSKIP, bool KLIM>
__global__ void __launch_bounds__(256, 1)
gemmH(const h16* __restrict__ Ah, const h16* __restrict__ Al,
      const h16* __restrict__ Bh, const h16* __restrict__ Bl,
      float* __restrict__ C, int K, int lda, int ldb, int ldc,
      long long sA, long long sB, long long sC)
{
    constexpr int PITCH = 72;            // 64 + 8 pad (144B rows)
    constexpr int BUF   = 128 * PITCH;   // elems per operand buffer
    constexpr int NBUF  = (TERMS == 3) ? 4 : 3;
    constexpr int STAGE = NBUF * BUF;

    const int m0 = blockIdx.y << 7, n0 = blockIdx.x << 7;
    if (CSKIP && n0 >= m0 + 128) return;
    const int b = blockIdx.z;
    Ah += (long long)b * sA; Al += (long long)b * sA;
    Bh += (long long)b * sB;
    if (TERMS == 3) Bl += (long long)b * sB;
    C += (long long)b * sC;
    const int Kend = KLIM ? ((m0 + 128 < K) ? m0 + 128 : K) : K;
    const int nK = Kend >> 6;

    extern __shared__ h16 sm[];
    const int tid = threadIdx.x, wid = tid >> 5;
    const int wm = (wid & 3) << 5;    // 4 warps over M, 32 rows each
    const int wn = (wid >> 2) << 6;   // 2 warps over N, 64 cols each

    auto load_stage = [&](int st, int kc) {
        const int k0 = kc << 6;
        h16* base = sm + st * STAGE;
        #pragma unroll
        for (int i = 0; i < NBUF * 4; i++) {
            int c   = tid + (i << 8);
            int buf = c >> 10;            // 1024 cp16 per operand buffer
            int r   = (c >> 3) & 127;
            int k8  = (c & 7) << 3;
            h16* dst = base + buf * BUF + r * PITCH + k8;
            const h16* g;
            if      (buf == 0) g = Ah + (long long)(m0 + r) * lda + k0 + k8;
            else if (buf == 1) g = Al + (long long)(m0 + r) * lda + k0 + k8;
            else if (buf == 2) g = Bh + (long long)(n0 + r) * ldb + k0 + k8;
            else               g = Bl + (long long)(n0 + r) * ldb + k0 + k8;
            cp16(dst, g);
        }
        asm volatile("cp.async.commit_group;");
    };

    wmma::fragment<wmma::accumulator, 16, 16, 16, float> acc[2][4];
    #pragma unroll
    for (int i = 0; i < 2; i++)
        #pragma unroll
        for (int j = 0; j < 4; j++)
            wmma::fill_fragment(acc[i][j], 0.0f);

    load_stage(0, 0);
    if (nK > 1) load_stage(1, 1);

    for (int kt = 0; kt < nK; kt++) {
        if (kt == nK - 1) asm volatile("cp.async.wait_group 0;");
        else              asm volatile("cp.async.wait_group 1;");
        __syncthreads();

        const h16* base = sm + (kt % 3) * STAGE;
        const h16* sAh_ = base;
        const h16* sAl_ = base + BUF;
        const h16* sBh_ = base + 2 * BUF;
        const h16* sBl_ = base + 3 * BUF;

        #pragma unroll
        for (int kk = 0; kk < 4; kk++) {
            const int ko = kk << 4;
            wmma::fragment<wmma::matrix_a, 16, 16, 16, h16, wmma::row_major> ah[2], al[2];
            #pragma unroll
            for (int i = 0; i < 2; i++) {
                wmma::load_matrix_sync(ah[i], sAh_ + (wm + (i << 4)) * PITCH + ko, PITCH);
                wmma::load_matrix_sync(al[i], sAl_ + (wm + (i << 4)) * PITCH + ko, PITCH);
            }
            #pragma unroll
            for (int j = 0; j < 4; j++) {
                wmma::fragment<wmma::matrix_b, 16, 16, 16, h16, wmma::col_major> bf;
                wmma::load_matrix_sync(bf, sBh_ + (wn + (j << 4)) * PITCH + ko, PITCH);
                #pragma unroll
                for (int i = 0; i < 2; i++) {
                    wmma::mma_sync(acc[i][j], ah[i], bf, acc[i][j]);
                    wmma::mma_sync(acc[i][j], al[i], bf, acc[i][j]);
                }
                if (TERMS == 3) {
                    wmma::load_matrix_sync(bf, sBl_ + (wn + (j << 4)) * PITCH + ko, PITCH);
                    #pragma unroll
                    for (int i = 0; i < 2; i++)
                        wmma::mma_sync(acc[i][j], ah[i], bf, acc[i][j]);
                }
            }
        }
        __syncthreads();
        if (kt + 2 < nK) load_stage((kt + 2) % 3, kt + 2);
    }

    #pragma unroll
    for (int i = 0; i < 2; i++)
        #pragma unroll
        for (int j = 0; j < 4; j++)
            wmma::store_matrix_sync(
                &C[(long long)(m0 + wm + (i << 4)) * ldc + n0 + wn + (j << 4)],
                acc[i][j], ldc, wmma::mem_row_major);
}

template <int TERMS, bool CSKIP, bool KLIM>
static void rung(const h16* Ah, const h16* Al, const h16* Bh, const h16* Bl,
                 float* C, int M, int N, int K, int lda, int ldb, int ldc,
                 long long sA, long long sB, long long sC, int batch)
{
    constexpr int NBUF = (TERMS == 3) ? 4 : 3;
    size_t smem = 3ull * NBUF * 128 * 72 * sizeof(h16);
    cudaFuncSetAttribute(gemmH<TERMS, CSKIP, KLIM>,
                         cudaFuncAttributeMaxDynamicSharedMemorySize, (int)smem);
    dim3 grid(N / 128, M / 128, batch);
    gemmH<TERMS, CSKIP, KLIM><<<grid, 256, smem>>>(Ah, Al, Bh, Bl, C,
                                                   K, lda, ldb, ldc, sA, sB, sC);
}

// ---------------- split fp32 -> (fp16 hi, fp16 lo) ----------------------------
__global__ void split_kernel(const float4* __restrict__ src,
                             __half2* __restrict__ h,
                             __half2* __restrict__ l, int n4)
{
    int i = blockIdx.x * blockDim.x + threadIdx.x;
    if (i >= n4) return;
    float4 v = src[i];
    h16 h0 = __float2half_rn(v.x), h1 = __float2half_rn(v.y);
    h16 h2 = __float2half_rn(v.z), h3 = __float2half_rn(v.w);
    h16 l0 = __float2half_rn(v.x - __half2float(h0));
    h16 l1 = __float2half_rn(v.y - __half2float(h1));
    h16 l2 = __float2half_rn(v.z - __half2float(h2));
    h16 l3 = __float2half_rn(v.w - __half2float(h3));
    h[2*i]   = __halves2half2(h0, h1);
    h[2*i+1] = __halves2half2(h2, h3);
    l[2*i]   = __halves2half2(l0, l1);
    l[2*i+1] = __halves2half2(l2, l3);
}
static void split(const float* src, h16* h, h16* l, long long n)
{
    int n4 = (int)(n / 4);
    split_kernel<<<(n4 + 255) / 256, 256>>>((const float4*)src,
                                            (__half2*)h, (__half2*)l, n4);
}

// ---------------- transpose + split: src[R][C] fp32 -> dst[C][R] fp16 ----------
template <bool LO>
__global__ void tsplit_kernel(const float* __restrict__ src, int ld_src,
                              h16* __restrict__ dh, h16* __restrict__ dl,
                              int ld_dst, long long sSrc, long long sDst)
{
    __shared__ float t[32][33];
    const float* s = src + (long long)blockIdx.z * sSrc;
    h16* oh = dh + (long long)blockIdx.z * sDst;
    h16* ol = dl + (long long)blockIdx.z * sDst;
    int r0 = blockIdx.x * 32;
    int c0 = blockIdx.y * 32;
    int tx = threadIdx.x, ty = threadIdx.y;
    #pragma unroll
    for (int j = 0; j < 4; j++)
        t[ty + j * 8][tx] = s[(long long)(r0 + ty + j * 8) * ld_src + c0 + tx];
    __syncthreads();
    #pragma unroll
    for (int j = 0; j < 4; j++) {
        float v = t[tx][ty + j * 8];
        long long o = (long long)(c0 + ty + j * 8) * ld_dst + r0 + tx;
        h16 hi = __float2half_rn(v);
        oh[o] = hi;
        if (LO) ol[o] = __float2half_rn(v - __half2float(hi));
    }
}
template <bool LO>
static void tsplit(const float* src, int R, int Cc, int ld_src,
                   h16* dh, h16* dl, int ld_dst,
                   long long sSrc, long long sDst, int batch)
{
    dim3 grid(R / 32, Cc / 32, batch), block(32, 8);
    tsplit_kernel<LO><<<grid, block>>>(src, ld_src, dh, dl, ld_dst, sSrc, sDst);
}

// ---------------- rmsnorm (in-place) -------------------------------------------
__global__ void rmsnorm_kernel(float* __restrict__ x, const float* __restrict__ w,
                               int len, int stride)
{
    float* row = x + (long long)blockIdx.x * stride;
    __shared__ float red[256];
    int tid = threadIdx.x;
    float ss = 0.f;
    for (int j = tid; j < len; j += 256) { float v = row[j]; ss += v * v; }
    red[tid] = ss; __syncthreads();
    for (int s = 128; s > 0; s >>= 1) {
        if (tid < s) red[tid] += red[tid + s];
        __syncthreads();
    }
    float rr = rsqrtf(red[0] / (float)len + 1e-6f);
    for (int j = tid; j < len; j += 256) row[j] = row[j] * rr * w[j];
}

// ---------------- RoPE ----------------------------------------------------------
__global__ void rope_q_kernel(float* __restrict__ q)
{
    int idx = blockIdx.x * blockDim.x + threadIdx.x;
    if (idx >= SQ * NH * 32) return;
    int dp = idx & 31;
    int h  = (idx >> 5) & 127;
    int s  = idx >> 12;
    float a = (float)s * __expf(-(float)dp * (logf(10000.f) / 32.f));
    float c, sn;
    sincosf(a, &sn, &c);
    float* base = q + (long long)s * (NH * DQ) + h * DQ + DN;
    float x1 = base[dp], x2 = base[dp + 32];
    base[dp]      = x1 * c - x2 * sn;
    base[dp + 32] = x2 * c + x1 * sn;
}
__global__ void rope_kpe_kernel(const float* __restrict__ kva, float* __restrict__ kpe)
{
    int idx = blockIdx.x * blockDim.x + threadIdx.x;
    if (idx >= SQ * 32) return;
    int dp = idx & 31;
    int s  = idx >> 5;
    float a = (float)s * __expf(-(float)dp * (logf(10000.f) / 32.f));
    float c, sn;
    sincosf(a, &sn, &c);
    const float* src = kva + (long long)s * KVAP + KVLORA;
    float x1 = src[dp], x2 = src[dp + 32];
    kpe[s * DR + dp]      = x1 * c - x2 * sn;
    kpe[s * DR + dp + 32] = x2 * c + x1 * sn;
}

// ---------------- assemble K_full -> fp16 hi/lo ---------------------------------
__global__ void assemble_k_split_kernel(const float* __restrict__ kv,
                                        const float* __restrict__ kpe,
                                        h16* __restrict__ kh, h16* __restrict__ kl)
{
    long long idx = (long long)blockIdx.x * blockDim.x + threadIdx.x;
    if (idx >= (long long)NH * SQ * DQ) return;
    int d = (int)(idx % DQ);
    int j = (int)((idx / DQ) % SQ);
    int h = (int)(idx / ((long long)DQ * SQ));
    float v;
    if (d < DN) v = kv[(long long)j * (NH * 256) + h * 256 + d];
    else        v = kpe[j * DR + (d - DN)];
    h16 hi = __float2half_rn(v);
    kh[idx] = hi;
    kl[idx] = __float2half_rn(v - __half2float(hi));
}

// ---------------- causal softmax + split to fp16 hi/lo --------------------------
__global__ void softmax_split_kernel(const float* __restrict__ scores,
                                     h16* __restrict__ Ph, h16* __restrict__ Pl)
{
    int r = blockIdx.x;                 // h*1024 + i
    int i = r & (SQ - 1);
    const float* row = scores + (long long)r * SQ;
    h16* ph = Ph + (long long)r * SQ;
    h16* pl = Pl + (long long)r * SQ;
    const float scale = 0.07216878365f; // 1/sqrt(192)
    int tid = threadIdx.x;
    int lane = tid & 31, warp = tid >> 5;
    __shared__ float redm[8], reds[8];

    float v[4];
    #pragma unroll
    for (int t = 0; t < 4; t++) {
        int j = tid + t * 256;
        v[t] = (j <= i) ? row[j] * scale : -FLT_MAX;
    }
    float mx = fmaxf(fmaxf(v[0], v[1]), fmaxf(v[2], v[3]));
    #pragma unroll
    for (int o = 16; o > 0; o >>= 1) mx = fmaxf(mx, __shfl_xor_sync(~0u, mx, o));
    if (lane == 0) redm[warp] = mx;
    __syncthreads();
    mx = redm[0];
    #pragma unroll
    for (int w = 1; w < 8; w++) mx = fmaxf(mx, redm[w]);

    float e[4];
    float sum = 0.f;
    #pragma unroll
    for (int t = 0; t < 4; t++) {
        int j = tid + t * 256;
        e[t] = (j <= i) ? __expf(v[t] - mx) : 0.f;
        sum += e[t];
    }
    #pragma unroll
    for (int o = 16; o > 0; o >>= 1) sum += __shfl_xor_sync(~0u, sum, o);
    if (lane == 0) reds[warp] = sum;
    __syncthreads();
    sum = 0.f;
    #pragma unroll
    for (int w = 0; w < 8; w++) sum += reds[w];
    float inv = 1.f / sum;

    #pragma unroll
    for (int t = 0; t < 4; t++) {
        int j = tid + t * 256;
        float p = e[t] * inv;
        h16 hi = __float2half_rn(p);
        ph[j] = hi;
        pl[j] = __float2half_rn(p - __half2float(hi));
    }
}

// ---------------- host side -----------------------------------------------------
extern "C" void kernel_launch(void* const* d_in, const int* in_sizes, int n_in,
                              void* d_out, int out_size)
{
    const float* x     = (const float*)d_in[0];
    const float* Wqa   = (const float*)d_in[2];   // [7168,1536]
    const float* wqln  = (const float*)d_in[3];
    const float* Wqb   = (const float*)d_in[4];   // [1536,24576]
    const float* Wkva  = (const float*)d_in[5];   // [7168,576]
    const float* wkvln = (const float*)d_in[6];
    const float* Wkvb  = (const float*)d_in[7];   // [512,32768]
    const float* Wo    = (const float*)d_in[8];   // [16384,7168]
    float*       out   = (float*)d_out;

    float *qa, *kva, *kpe, *q, *kv, *scores, *attnout;
    cudaGetSymbolAddress((void**)&qa,      g_qa);
    cudaGetSymbolAddress((void**)&kva,     g_kva);
    cudaGetSymbolAddress((void**)&kpe,     g_kpe);
    cudaGetSymbolAddress((void**)&q,       g_q);
    cudaGetSymbolAddress((void**)&kv,      g_kv);
    cudaGetSymbolAddress((void**)&scores,  g_scores);
    cudaGetSymbolAddress((void**)&attnout, g_attnout);

    h16 *xh,*xl,*qah,*qal,*kvah,*kval,*qh,*ql,*kh,*kl,*Phb,*Plb,*aoh,*aol;
    h16 *Wqat_h,*Wqat_l,*Wkvat_h,*Wkvat_l,*Wqbt_h,*Wkvbt_h,*Wot_h,*Vt_h,*Vt_l;
    cudaGetSymbolAddress((void**)&xh,   g_xh);    cudaGetSymbolAddress((void**)&xl,   g_xl);
    cudaGetSymbolAddress((void**)&qah,  g_qah);   cudaGetSymbolAddress((void**)&qal,  g_qal);
    cudaGetSymbolAddress((void**)&kvah, g_kvah);  cudaGetSymbolAddress((void**)&kval, g_kval);
    cudaGetSymbolAddress((void**)&qh,   g_qh);    cudaGetSymbolAddress((void**)&ql,   g_ql);
    cudaGetSymbolAddress((void**)&kh,   g_kh);    cudaGetSymbolAddress((void**)&kl,   g_kl);
    cudaGetSymbolAddress((void**)&Phb,  g_Ph);    cudaGetSymbolAddress((void**)&Plb,  g_Pl);
    cudaGetSymbolAddress((void**)&aoh,  g_aoh);   cudaGetSymbolAddress((void**)&aol,  g_aol);
    cudaGetSymbolAddress((void**)&Wqat_h,  g_Wqa_t_h);  cudaGetSymbolAddress((void**)&Wqat_l,  g_Wqa_t_l);
    cudaGetSymbolAddress((void**)&Wkvat_h, g_Wkva_t_h); cudaGetSymbolAddress((void**)&Wkvat_l, g_Wkva_t_l);
    cudaGetSymbolAddress((void**)&Wqbt_h,  g_Wqb_t_h);
    cudaGetSymbolAddress((void**)&Wkvbt_h, g_Wkvb_t_h);
    cudaGetSymbolAddress((void**)&Wot_h,   g_Wo_t_h);
    cudaGetSymbolAddress((void**)&Vt_h,    g_Vt_h);     cudaGetSymbolAddress((void**)&Vt_l,    g_Vt_l);

    // 0) split x; transpose(+split) weights into [N][K] K-major fp16
    split(x, xh, xl, (long long)SQ * HID);
    tsplit<true >(Wqa,  HID,    QLORA,    QLORA,    Wqat_h,  Wqat_l, HID,    0, 0, 1);
    tsplit<true >(Wkva, HID,    576,      576,      Wkvat_h, Wkvat_l,HID,    0, 0, 1); // pad rows 576..639 stay zero
    tsplit<false>(Wqb,  QLORA,  NH * DQ,  NH * DQ,  Wqbt_h,  Wqbt_h, QLORA,  0, 0, 1);
    tsplit<false>(Wkvb, KVLORA, NH * 256, NH * 256, Wkvbt_h, Wkvbt_h,KVLORA, 0, 0, 1);
    tsplit<false>(Wo,   NH*DV,  HID,      HID,      Wot_h,   Wot_h,  NH*DV,  0, 0, 1);

    // 1) down-projections (3-term)
    rung<3,false,false>(xh, xl, Wqat_h, Wqat_l, qa,
        SQ, QLORA, HID, HID, HID, QLORA, 0, 0, 0, 1);
    rung<3,false,false>(xh, xl, Wkvat_h, Wkvat_l, kva,
        SQ, KVAP, HID, HID, HID, KVAP, 0, 0, 0, 1);

    // 2) k_pe rope (pre-norm cols 512..575) + rmsnorms
    rope_kpe_kernel<<<(SQ * 32 + 255) / 256, 256>>>(kva, kpe);
    rmsnorm_kernel<<<SQ, 256>>>(qa,  wqln,  QLORA,  QLORA);
    rmsnorm_kernel<<<SQ, 256>>>(kva, wkvln, KVLORA, KVAP);

    // 3) split activations; up-projections (2-term)
    split(qa,  qah,  qal,  (long long)SQ * QLORA);
    split(kva, kvah, kval, (long long)SQ * KVAP);
    rung<2,false,false>(qah, qal, Wqbt_h, Wqbt_h, q,
        SQ, NH * DQ, QLORA, QLORA, QLORA, NH * DQ, 0, 0, 0, 1);
    rung<2,false,false>(kvah, kval, Wkvbt_h, Wkvbt_h, kv,
        SQ, NH * 256, KVLORA, KVAP, KVLORA, NH * 256, 0, 0, 0, 1);

    // 4) RoPE on q; operand prep
    rope_q_kernel<<<(SQ * NH * 32 + 255) / 256, 256>>>(q);
    split(q, qh, ql, (long long)SQ * NH * DQ);
    assemble_k_split_kernel<<<(int)(((long long)NH * SQ * DQ + 255) / 256), 256>>>(kv, kpe, kh, kl);
    tsplit<true>(kv + DN, SQ, DV, NH * 256, Vt_h, Vt_l, SQ,
                 256, (long long)DV * SQ, NH);

    // 5) scores = Q @ K^T (3-term, causal tile-skip)
    rung<3,true,false>(qh, ql, kh, kl, scores,
        SQ, SQ, DQ, NH * DQ, DQ, SQ,
        DQ, (long long)SQ * DQ, (long long)SQ * SQ, NH);

    // 6) causal softmax + split
    softmax_split_kernel<<<NH * SQ, 256>>>(scores, Phb, Plb);

    // 7) out_h = P @ V (3-term, k-limited by causality)
    rung<3,false,true>(Phb, Plb, Vt_h, Vt_l, attnout,
        SQ, DV, SQ, SQ, SQ, NH * DV,
        (long long)SQ * SQ, (long long)DV * SQ, DV, NH);

    // 8) output projection (2-term)
    split(attnout, aoh, aol, (long long)SQ * NH * DV);
    rung<2,false,false>(aoh, aol, Wot_h, Wot_h, out,
        SQ, HID, NH * DV, NH * DV, NH * DV, HID, 0, 0, 0, 1);
}

// round 8
// speedup vs baseline: 8.1073x; 1.1895x over previous
#include <cuda_runtime.h>
#include <cuda_fp16.h>
#include <mma.h>
#include <cfloat>
#include <cstdint>
#include <math.h>

using namespace nvcuda;
typedef __half h16;

#define SQ   1024
#define NH   128
#define DQ   192
#define DN   128
#define DR   64
#define DV   128
#define HID  7168
#define QLORA 1536
#define KVLORA 512
#define KVAP 640            // padded kv_a width (576 -> 640)
#define DPN  (QLORA + KVAP) // combined down-proj width = 2176 (17 * 128)

// ---------------- scratch (device globals; allocation-free rule) -------------
__device__ float g_qkva[SQ * DPN];        // [qa | kva] combined
__device__ float g_kpe[SQ * DR];
__device__ float g_q[SQ * NH * DQ];
__device__ float g_kv[SQ * NH * 256];
__device__ float g_attnout[SQ * NH * DV];
__device__ float g_scores[(long long)NH * SQ * SQ];

// fp16 hi/lo activations
__device__ h16 g_xh[SQ * HID],        g_xl[SQ * HID];
__device__ h16 g_qkvah[SQ * DPN],     g_qkval[SQ * DPN];
__device__ h16 g_qh[SQ * NH * DQ],    g_ql[SQ * NH * DQ];
__device__ h16 g_kh[(long long)NH * SQ * DQ], g_kl[(long long)NH * SQ * DQ];
__device__ h16 g_Ph[(long long)NH * SQ * SQ];        // P hi only
__device__ h16 g_aoh[SQ * NH * DV],   g_aol[SQ * NH * DV];

// fp16 transposed weights ([N][K] K-major)
__device__ h16 g_Wdt_h[(long long)DPN * HID], g_Wdt_l[(long long)DPN * HID]; // [Wqa|Wkva]^T
__device__ h16 g_Wqb_t_h[NH * DQ * QLORA];
__device__ h16 g_Wkvb_t_h[NH * 256 * KVLORA];
__device__ h16 g_Wo_t_h[(long long)HID * NH * DV];
__device__ h16 g_Vt_h[(long long)NH * DV * SQ], g_Vt_l[(long long)NH * DV * SQ];

// ---------------- helpers -----------------------------------------------------
__device__ __forceinline__ void cp16(const h16* smem_dst, const h16* gsrc) {
    unsigned int saddr = (unsigned int)__cvta_generic_to_shared(smem_dst);
    asm volatile("cp.async.cg.shared.global [%0], [%1], 16;\n" :: "r"(saddr), "l"(gsrc));
}

// ---------------- mixed-term fp16 GEMM -----------------------------------------
// C[M,N] = A[M,K] @ B[N,K]^T  (K-major fp16; batch via blockIdx.z)
// Terms: Ah*Bh  (+ Al*Bh if TA==2)  (+ Ah*Bl if TB==2)
// TA+TB==3 -> 2-stage pipeline, 2 CTAs/SM; TA+TB==4 -> 3-stage, 1 CTA/SM.
template <int TA, int TB, bool CSKIP, bool KLIM>
__global__ void __launch_bounds__(256, (TA + TB == 4) ? 1 : 2)
gemmH(const h16* __restrict__ Ah, const h16* __restrict__ Al,
      const h16* __restrict__ Bh, const h16* __restrict__ Bl,
      float* __restrict__ C, int K, int lda, int ldb, int ldc,
      long long sA, long long sB, long long sC)
{
    constexpr int PITCH  = 72;           // 64 + 8 pad
    constexpr int BUF    = 128 * PITCH;
    constexpr int NBUF   = TA + TB;
    constexpr int NSTAGE = (NBUF == 4) ? 3 : 2;
    constexpr int STAGE  = NBUF * BUF;

    const int m0 = blockIdx.y << 7, n0 = blockIdx.x << 7;
    if (CSKIP && n0 >= m0 + 128) return;
    const int b = blockIdx.z;
    Ah += (long long)b * sA;
    if (TA == 2) Al += (long long)b * sA;
    Bh += (long long)b * sB;
    if (TB == 2) Bl += (long long)b * sB;
    C += (long long)b * sC;
    const int Kend = KLIM ? ((m0 + 128 < K) ? m0 + 128 : K) : K;
    const int nK = Kend >> 6;

    extern __shared__ h16 sm[];
    const int tid = threadIdx.x, wid = tid >> 5;
    const int wm = (wid & 3) << 5;
    const int wn = (wid >> 2) << 6;

    auto load_stage = [&](int st, int kc) {
        const int k0 = kc << 6;
        h16* base = sm + st * STAGE;
        #pragma unroll
        for (int i = 0; i < NBUF * 4; i++) {
            int c   = tid + (i << 8);
            int buf = c >> 10;
            int r   = (c >> 3) & 127;
            int k8  = (c & 7) << 3;
            h16* dst = base + buf * BUF + r * PITCH + k8;
            long long offA = (long long)(m0 + r) * lda + k0 + k8;
            long long offB = (long long)(n0 + r) * ldb + k0 + k8;
            const h16* g;
            if (TA == 2) {
                if      (buf == 0) g = Ah + offA;
                else if (buf == 1) g = Al + offA;
                else if (buf == 2) g = Bh + offB;
                else               g = Bl + offB;
            } else {
                if      (buf == 0) g = Ah + offA;
                else if (buf == 1) g = Bh + offB;
                else               g = Bl + offB;
            }
            cp16(dst, g);
        }
        asm volatile("cp.async.commit_group;");
    };

    wmma::fragment<wmma::accumulator, 16, 16, 16, float> acc[2][4];
    #pragma unroll
    for (int i = 0; i < 2; i++)
        #pragma unroll
        for (int j = 0; j < 4; j++)
            wmma::fill_fragment(acc[i][j], 0.0f);

    auto compute = [&](int st) {
        const h16* base = sm + st * STAGE;
        const h16* sAh_ = base;
        const h16* sAl_ = base + BUF;                 // valid iff TA==2
        const h16* sBh_ = base + TA * BUF;
        const h16* sBl_ = base + (TA + 1) * BUF;      // valid iff TB==2
        #pragma unroll
        for (int kk = 0; kk < 4; kk++) {
            const int ko = kk << 4;
            wmma::fragment<wmma::matrix_a, 16, 16, 16, h16, wmma::row_major> ah[2], al[2];
            #pragma unroll
            for (int i = 0; i < 2; i++) {
                wmma::load_matrix_sync(ah[i], sAh_ + (wm + (i << 4)) * PITCH + ko, PITCH);
                if (TA == 2)
                    wmma::load_matrix_sync(al[i], sAl_ + (wm + (i << 4)) * PITCH + ko, PITCH);
            }
            #pragma unroll
            for (int j = 0; j < 4; j++) {
                wmma::fragment<wmma::matrix_b, 16, 16, 16, h16, wmma::col_major> bf;
                wmma::load_matrix_sync(bf, sBh_ + (wn + (j << 4)) * PITCH + ko, PITCH);
                #pragma unroll
                for (int i = 0; i < 2; i++) {
                    wmma::mma_sync(acc[i][j], ah[i], bf, acc[i][j]);
                    if (TA == 2) wmma::mma_sync(acc[i][j], al[i], bf, acc[i][j]);
                }
                if (TB == 2) {
                    wmma::load_matrix_sync(bf, sBl_ + (wn + (j << 4)) * PITCH + ko, PITCH);
                    #pragma unroll
                    for (int i = 0; i < 2; i++)
                        wmma::mma_sync(acc[i][j], ah[i], bf, acc[i][j]);
                }
            }
        }
    };

    if (NSTAGE == 2) {
        load_stage(0, 0);
        for (int kt = 0; kt < nK; kt++) {
            if (kt + 1 < nK) {
                load_stage((kt + 1) & 1, kt + 1);
                asm volatile("cp.async.wait_group 1;");
            } else {
                asm volatile("cp.async.wait_group 0;");
            }
            __syncthreads();
            compute(kt & 1);
            __syncthreads();
        }
    } else {
        load_stage(0, 0);
        if (nK > 1) load_stage(1, 1);
        for (int kt = 0; kt < nK; kt++) {
            if (kt == nK - 1) asm volatile("cp.async.wait_group 0;");
            else              asm volatile("cp.async.wait_group 1;");
            __syncthreads();
            compute(kt % 3);
            __syncthreads();
            if (kt + 2 < nK) load_stage((kt + 2) % 3, kt + 2);
        }
    }

    #pragma unroll
    for (int i = 0; i < 2; i++)
        #pragma unroll
        for (int j = 0; j < 4; j++)
            wmma::store_matrix_sync(
                &C[(long long)(m0 + wm + (i << 4)) * ldc + n0 + wn + (j << 4)],
                acc[i][j], ldc, wmma::mem_row_major);
}

template <int TA, int TB, bool CSKIP, bool KLIM>
static void rung(const h16* Ah, const h16* Al, const h16* Bh, const h16* Bl,
                 float* C, int M, int N, int K, int lda, int ldb, int ldc,
                 long long sA, long long sB, long long sC, int batch)
{
    constexpr int NBUF   = TA + TB;
    constexpr int NSTAGE = (NBUF == 4) ? 3 : 2;
    size_t smem = (size_t)NSTAGE * NBUF * 128 * 72 * sizeof(h16);
    cudaFuncSetAttribute(gemmH<TA, TB, CSKIP, KLIM>,
                         cudaFuncAttributeMaxDynamicSharedMemorySize, (int)smem);
    dim3 grid(N / 128, M / 128, batch);
    gemmH<TA, TB, CSKIP, KLIM><<<grid, 256, smem>>>(Ah, Al, Bh, Bl, C,
                                                    K, lda, ldb, ldc, sA, sB, sC);
}

// ---------------- split fp32 -> (fp16 hi, fp16 lo) ----------------------------
__global__ void split_kernel(const float4* __restrict__ src,
                             __half2* __restrict__ h,
                             __half2* __restrict__ l, int n4)
{
    int i = blockIdx.x * blockDim.x + threadIdx.x;
    if (i >= n4) return;
    float4 v = src[i];
    h16 h0 = __float2half_rn(v.x), h1 = __float2half_rn(v.y);
    h16 h2 = __float2half_rn(v.z), h3 = __float2half_rn(v.w);
    h16 l0 = __float2half_rn(v.x - __half2float(h0));
    h16 l1 = __float2half_rn(v.y - __half2float(h1));
    h16 l2 = __float2half_rn(v.z - __half2float(h2));
    h16 l3 = __float2half_rn(v.w - __half2float(h3));
    h[2*i]   = __halves2half2(h0, h1);
    h[2*i+1] = __halves2half2(h2, h3);
    l[2*i]   = __halves2half2(l0, l1);
    l[2*i+1] = __halves2half2(l2, l3);
}
static void split(const float* src, h16* h, h16* l, long long n)
{
    int n4 = (int)(n / 4);
    split_kernel<<<(n4 + 255) / 256, 256>>>((const float4*)src,
                                            (__half2*)h, (__half2*)l, n4);
}

// ---------------- transpose + split: src[R][C] fp32 -> dst[C][R] fp16 ----------
template <bool LO>
__global__ void tsplit_kernel(const float* __restrict__ src, int ld_src,
                              h16* __restrict__ dh, h16* __restrict__ dl,
                              int ld_dst, long long sSrc, long long sDst)
{
    __shared__ float t[32][33];
    const float* s = src + (long long)blockIdx.z * sSrc;
    h16* oh = dh + (long long)blockIdx.z * sDst;
    h16* ol = dl + (long long)blockIdx.z * sDst;
    int r0 = blockIdx.x * 32;
    int c0 = blockIdx.y * 32;
    int tx = threadIdx.x, ty = threadIdx.y;
    #pragma unroll
    for (int j = 0; j < 4; j++)
        t[ty + j * 8][tx] = s[(long long)(r0 + ty + j * 8) * ld_src + c0 + tx];
    __syncthreads();
    #pragma unroll
    for (int j = 0; j < 4; j++) {
        float v = t[tx][ty + j * 8];
        long long o = (long long)(c0 + ty + j * 8) * ld_dst + r0 + tx;
        h16 hi = __float2half_rn(v);
        oh[o] = hi;
        if (LO) ol[o] = __float2half_rn(v - __half2float(hi));
    }
}
template <bool LO>
static void tsplit(const float* src, int R, int Cc, int ld_src,
                   h16* dh, h16* dl, int ld_dst,
                   long long sSrc, long long sDst, int batch)
{
    dim3 grid(R / 32, Cc / 32, batch), block(32, 8);
    tsplit_kernel<LO><<<grid, block>>>(src, ld_src, dh, dl, ld_dst, sSrc, sDst);
}

// ---------------- rmsnorm (in-place, strided) -----------------------------------
__global__ void rmsnorm_kernel(float* __restrict__ x, const float* __restrict__ w,
                               int len, int stride)
{
    float* row = x + (long long)blockIdx.x * stride;
    __shared__ float red[256];
    int tid = threadIdx.x;
    float ss = 0.f;
    for (int j = tid; j < len; j += 256) { float v = row[j]; ss += v * v; }
    red[tid] = ss; __syncthreads();
    for (int s = 128; s > 0; s >>= 1) {
        if (tid < s) red[tid] += red[tid + s];
        __syncthreads();
    }
    float rr = rsqrtf(red[0] / (float)len + 1e-6f);
    for (int j = tid; j < len; j += 256) row[j] = row[j] * rr * w[j];
}

// ---------------- RoPE ----------------------------------------------------------
__global__ void rope_q_kernel(float* __restrict__ q)
{
    int idx = blockIdx.x * blockDim.x + threadIdx.x;
    if (idx >= SQ * NH * 32) return;
    int dp = idx & 31;
    int h  = (idx >> 5) & 127;
    int s  = idx >> 12;
    float a = (float)s * __expf(-(float)dp * (logf(10000.f) / 32.f));
    float c, sn;
    sincosf(a, &sn, &c);
    float* base = q + (long long)s * (NH * DQ) + h * DQ + DN;
    float x1 = base[dp], x2 = base[dp + 32];
    base[dp]      = x1 * c - x2 * sn;
    base[dp + 32] = x2 * c + x1 * sn;
}
// src points at k_pe col 0 of row 0; row stride passed explicitly
__global__ void rope_kpe_kernel(const float* __restrict__ src0, int stride,
                                float* __restrict__ kpe)
{
    int idx = blockIdx.x * blockDim.x + threadIdx.x;
    if (idx >= SQ * 32) return;
    int dp = idx & 31;
    int s  = idx >> 5;
    float a = (float)s * __expf(-(float)dp * (logf(10000.f) / 32.f));
    float c, sn;
    sincosf(a, &sn, &c);
    const float* src = src0 + (long long)s * stride;
    float x1 = src[dp], x2 = src[dp + 32];
    kpe[s * DR + dp]      = x1 * c - x2 * sn;
    kpe[s * DR + dp + 32] = x2 * c + x1 * sn;
}

// ---------------- assemble K_full -> fp16 hi/lo ---------------------------------
__global__ void assemble_k_split_kernel(const float* __restrict__ kv,
                                        const float* __restrict__ kpe,
                                        h16* __restrict__ kh, h16* __restrict__ kl)
{
    long long idx = (long long)blockIdx.x * blockDim.x + threadIdx.x;
    if (idx >= (long long)NH * SQ * DQ) return;
    int d = (int)(idx % DQ);
    int j = (int)((idx / DQ) % SQ);
    int h = (int)(idx / ((long long)DQ * SQ));
    float v;
    if (d < DN) v = kv[(long long)j * (NH * 256) + h * 256 + d];
    else        v = kpe[j * DR + (d - DN)];
    h16 hi = __float2half_rn(v);
    kh[idx] = hi;
    kl[idx] = __float2half_rn(v - __half2float(hi));
}

// ---------------- causal softmax -> fp16 P (hi only, bounded writes) ------------
__global__ void softmax_p_kernel(const float* __restrict__ scores,
                                 h16* __restrict__ Ph)
{
    int r = blockIdx.x;                 // h*1024 + i
    int i = r & (SQ - 1);
    const float* row = scores + (long long)r * SQ;
    h16* ph = Ph + (long long)r * SQ;
    const float scale = 0.07216878365f; // 1/sqrt(192)
    const int jmax = ((i >> 7) + 1) << 7;  // PV reads k < this bound
    int tid = threadIdx.x;
    int lane = tid & 31, warp = tid >> 5;
    __shared__ float redm[8], reds[8];

    float v[4];
    #pragma unroll
    for (int t = 0; t < 4; t++) {
        int j = tid + t * 256;
        v[t] = (j <= i) ? row[j] * scale : -FLT_MAX;
    }
    float mx = fmaxf(fmaxf(v[0], v[1]), fmaxf(v[2], v[3]));
    #pragma unroll
    for (int o = 16; o > 0; o >>= 1) mx = fmaxf(mx, __shfl_xor_sync(~0u, mx, o));
    if (lane == 0) redm[warp] = mx;
    __syncthreads();
    mx = redm[0];
    #pragma unroll
    for (int w = 1; w < 8; w++) mx = fmaxf(mx, redm[w]);

    float e[4];
    float sum = 0.f;
    #pragma unroll
    for (int t = 0; t < 4; t++) {
        int j = tid + t * 256;
        e[t] = (j <= i) ? __expf(v[t] - mx) : 0.f;
        sum += e[t];
    }
    #pragma unroll
    for (int o = 16; o > 0; o >>= 1) sum += __shfl_xor_sync(~0u, sum, o);
    if (lane == 0) reds[warp] = sum;
    __syncthreads();
    sum = 0.f;
    #pragma unroll
    for (int w = 0; w < 8; w++) sum += reds[w];
    float inv = 1.f / sum;

    #pragma unroll
    for (int t = 0; t < 4; t++) {
        int j = tid + t * 256;
        if (j < jmax) ph[j] = __float2half_rn(e[t] * inv);
    }
}

// ---------------- host side -----------------------------------------------------
extern "C" void kernel_launch(void* const* d_in, const int* in_sizes, int n_in,
                              void* d_out, int out_size)
{
    const float* x     = (const float*)d_in[0];
    const float* Wqa   = (const float*)d_in[2];   // [7168,1536]
    const float* wqln  = (const float*)d_in[3];
    const float* Wqb   = (const float*)d_in[4];   // [1536,24576]
    const float* Wkva  = (const float*)d_in[5];   // [7168,576]
    const float* wkvln = (const float*)d_in[6];
    const float* Wkvb  = (const float*)d_in[7];   // [512,32768]
    const float* Wo    = (const float*)d_in[8];   // [16384,7168]
    float*       out   = (float*)d_out;

    float *qkva, *kpe, *q, *kv, *scores, *attnout;
    cudaGetSymbolAddress((void**)&qkva,    g_qkva);
    cudaGetSymbolAddress((void**)&kpe,     g_kpe);
    cudaGetSymbolAddress((void**)&q,       g_q);
    cudaGetSymbolAddress((void**)&kv,      g_kv);
    cudaGetSymbolAddress((void**)&scores,  g_scores);
    cudaGetSymbolAddress((void**)&attnout, g_attnout);

    h16 *xh,*xl,*qkvah,*qkval,*qh,*ql,*kh,*kl,*Phb,*aoh,*aol;
    h16 *Wdt_h,*Wdt_l,*Wqbt_h,*Wkvbt_h,*Wot_h,*Vt_h,*Vt_l;
    cudaGetSymbolAddress((void**)&xh,    g_xh);    cudaGetSymbolAddress((void**)&xl,    g_xl);
    cudaGetSymbolAddress((void**)&qkvah, g_qkvah); cudaGetSymbolAddress((void**)&qkval, g_qkval);
    cudaGetSymbolAddress((void**)&qh,    g_qh);    cudaGetSymbolAddress((void**)&ql,    g_ql);
    cudaGetSymbolAddress((void**)&kh,    g_kh);    cudaGetSymbolAddress((void**)&kl,    g_kl);
    cudaGetSymbolAddress((void**)&Phb,   g_Ph);
    cudaGetSymbolAddress((void**)&aoh,   g_aoh);   cudaGetSymbolAddress((void**)&aol,   g_aol);
    cudaGetSymbolAddress((void**)&Wdt_h, g_Wdt_h); cudaGetSymbolAddress((void**)&Wdt_l, g_Wdt_l);
    cudaGetSymbolAddress((void**)&Wqbt_h,  g_Wqb_t_h);
    cudaGetSymbolAddress((void**)&Wkvbt_h, g_Wkvb_t_h);
    cudaGetSymbolAddress((void**)&Wot_h,   g_Wo_t_h);
    cudaGetSymbolAddress((void**)&Vt_h,    g_Vt_h); cudaGetSymbolAddress((void**)&Vt_l,  g_Vt_l);

    // 0) split x; transpose(+split) weights into [N][K] K-major fp16
    split(x, xh, xl, (long long)SQ * HID);
    tsplit<true >(Wqa,  HID,    QLORA,    QLORA,    Wdt_h,                    Wdt_l,                    HID,    0, 0, 1);
    tsplit<true >(Wkva, HID,    576,      576,      Wdt_h + (long long)QLORA*HID, Wdt_l + (long long)QLORA*HID, HID, 0, 0, 1);
    tsplit<false>(Wqb,  QLORA,  NH * DQ,  NH * DQ,  Wqbt_h,  Wqbt_h, QLORA,  0, 0, 1);
    tsplit<false>(Wkvb, KVLORA, NH * 256, NH * 256, Wkvbt_h, Wkvbt_h,KVLORA, 0, 0, 1);
    tsplit<false>(Wo,   NH*DV,  HID,      HID,      Wot_h,   Wot_h,  NH*DV,  0, 0, 1);

    // 1) combined down-projection (3-term): [qa | kva] = x @ [Wqa | Wkva]
    rung<2,2,false,false>(xh, xl, Wdt_h, Wdt_l, qkva,
        SQ, DPN, HID, HID, HID, DPN, 0, 0, 0, 1);

    // 2) k_pe rope (pre-norm cols QLORA+512 .. +575) + rmsnorms (strided views)
    rope_kpe_kernel<<<(SQ * 32 + 255) / 256, 256>>>(qkva + QLORA + KVLORA, DPN, kpe);
    rmsnorm_kernel<<<SQ, 256>>>(qkva,         wqln,  QLORA,  DPN);
    rmsnorm_kernel<<<SQ, 256>>>(qkva + QLORA, wkvln, KVLORA, DPN);

    // 3) split combined activations; up-projections (2-term, occ2)
    split(qkva, qkvah, qkval, (long long)SQ * DPN);
    rung<2,1,false,false>(qkvah, qkval, Wqbt_h, Wqbt_h, q,
        SQ, NH * DQ, QLORA, DPN, QLORA, NH * DQ, 0, 0, 0, 1);
    rung<2,1,false,false>(qkvah + QLORA, qkval + QLORA, Wkvbt_h, Wkvbt_h, kv,
        SQ, NH * 256, KVLORA, DPN, KVLORA, NH * 256, 0, 0, 0, 1);

    // 4) RoPE on q; operand prep
    rope_q_kernel<<<(SQ * NH * 32 + 255) / 256, 256>>>(q);
    split(q, qh, ql, (long long)SQ * NH * DQ);
    assemble_k_split_kernel<<<(int)(((long long)NH * SQ * DQ + 255) / 256), 256>>>(kv, kpe, kh, kl);
    tsplit<true>(kv + DN, SQ, DV, NH * 256, Vt_h, Vt_l, SQ,
                 256, (long long)DV * SQ, NH);

    // 5) scores = Q @ K^T (3-term, causal tile-skip)
    rung<2,2,true,false>(qh, ql, kh, kl, scores,
        SQ, SQ, DQ, NH * DQ, DQ, SQ,
        DQ, (long long)SQ * DQ, (long long)SQ * SQ, NH);

    // 6) causal softmax -> fp16 P (hi only)
    softmax_p_kernel<<<NH * SQ, 256>>>(scores, Phb);

    // 7) out_h = P @ V  ((1,2)-term: Ph*Vh + Ph*Vl, k-limited by causality)
    rung<1,2,false,true>(Phb, Phb, Vt_h, Vt_l, attnout,
        SQ, DV, SQ, SQ, SQ, NH * DV,
        (long long)SQ * SQ, (long long)DV * SQ, DV, NH);

    // 8) output projection (2-term, occ2)
    split(attnout, aoh, aol, (long long)SQ * NH * DV);
    rung<2,1,false,false>(aoh, aol, Wot_h, Wot_h, out,
        SQ, HID, NH * DV, NH * DV, NH * DV, HID, 0, 0, 0, 1);
}

// round 9
// speedup vs baseline: 10.0761x; 1.2428x over previous
#include <cuda_runtime.h>
#include <cuda_fp16.h>
#include <mma.h>
#include <cfloat>
#include <cstdint>
#include <math.h>

using namespace nvcuda;
typedef __half h16;

#define SQ   1024
#define NH   128
#define DQ   192
#define DN   128
#define DR   64
#define DV   128
#define HID  7168
#define QLORA 1536
#define KVLORA 512
#define KVAP 640            // padded kv_a width (576 -> 640)
#define DPN  (QLORA + KVAP) // combined down-proj width = 2176 (17 * 128)

// ---------------- scratch (device globals; allocation-free rule) -------------
__device__ float g_qkva[SQ * DPN];        // [qa | kva] combined
__device__ float g_kpe[SQ * DR];
__device__ float g_q[SQ * NH * DQ];
__device__ float g_kv[SQ * NH * 256];
__device__ float g_scores[(long long)NH * SQ * SQ];

// fp16 hi/lo activations
__device__ h16 g_xh[SQ * HID],        g_xl[SQ * HID];
__device__ h16 g_qkvah[SQ * DPN],     g_qkval[SQ * DPN];
__device__ h16 g_qh[SQ * NH * DQ],    g_ql[SQ * NH * DQ];
__device__ h16 g_kh[(long long)NH * SQ * DQ], g_kl[(long long)NH * SQ * DQ];
__device__ h16 g_Ph[(long long)NH * SQ * SQ];        // P hi only
__device__ h16 g_aoh[SQ * NH * DV];                  // attn out, fp16 hi only

// fp16 transposed weights ([N][K] K-major)
__device__ h16 g_Wdt_h[(long long)DPN * HID], g_Wdt_l[(long long)DPN * HID]; // [Wqa|Wkva]^T
__device__ h16 g_Wqb_t_h[NH * DQ * QLORA];
__device__ h16 g_Wkvb_t_h[NH * 256 * KVLORA];
__device__ h16 g_Wo_t_h[(long long)HID * NH * DV];
__device__ h16 g_Vt_h[(long long)NH * DV * SQ];

// ---------------- helpers -----------------------------------------------------
__device__ __forceinline__ void cp16(const h16* smem_dst, const h16* gsrc) {
    unsigned int saddr = (unsigned int)__cvta_generic_to_shared(smem_dst);
    asm volatile("cp.async.cg.shared.global [%0], [%1], 16;\n" :: "r"(saddr), "l"(gsrc));
}

// ---------------- mixed-term fp16 GEMM -----------------------------------------
// C[M,N] = A[M,K] @ B[N,K]^T  (K-major fp16; batch via blockIdx.z)
// Terms: Ah*Bh  (+ Al*Bh if TA==2)  (+ Ah*Bl if TB==2)
// HOUT: write fp16 (via smem staging) instead of fp32.
template <int TA, int TB, bool CSKIP, bool KLIM, bool HOUT>
__global__ void __launch_bounds__(256, (TA + TB == 4) ? 1 : 2)
gemmH(const h16* __restrict__ Ah, const h16* __restrict__ Al,
      const h16* __restrict__ Bh, const h16* __restrict__ Bl,
      float* __restrict__ C, int K, int lda, int ldb, int ldc,
      long long sA, long long sB, long long sC)
{
    constexpr int PITCH  = 72;           // 64 + 8 pad
    constexpr int BUF    = 128 * PITCH;
    constexpr int NBUF   = TA + TB;
    constexpr int NSTAGE = (NBUF == 4) ? 3 : 2;
    constexpr int STAGE  = NBUF * BUF;

    const int m0 = blockIdx.y << 7, n0 = blockIdx.x << 7;
    if (CSKIP && n0 >= m0 + 128) return;
    const int b = blockIdx.z;
    Ah += (long long)b * sA;
    if (TA == 2) Al += (long long)b * sA;
    Bh += (long long)b * sB;
    if (TB == 2) Bl += (long long)b * sB;
    const long long coff = (long long)b * sC;
    const int Kend = KLIM ? ((m0 + 128 < K) ? m0 + 128 : K) : K;
    const int nK = Kend >> 6;

    extern __shared__ h16 sm[];
    const int tid = threadIdx.x, wid = tid >> 5;
    const int wm = (wid & 3) << 5;
    const int wn = (wid >> 2) << 6;

    auto load_stage = [&](int st, int kc) {
        const int k0 = kc << 6;
        h16* base = sm + st * STAGE;
        #pragma unroll
        for (int i = 0; i < NBUF * 4; i++) {
            int c   = tid + (i << 8);
            int buf = c >> 10;
            int r   = (c >> 3) & 127;
            int k8  = (c & 7) << 3;
            h16* dst = base + buf * BUF + r * PITCH + k8;
            long long offA = (long long)(m0 + r) * lda + k0 + k8;
            long long offB = (long long)(n0 + r) * ldb + k0 + k8;
            const h16* g;
            if (TA == 2) {
                if      (buf == 0) g = Ah + offA;
                else if (buf == 1) g = Al + offA;
                else if (buf == 2) g = Bh + offB;
                else               g = Bl + offB;
            } else {
                if      (buf == 0) g = Ah + offA;
                else if (buf == 1) g = Bh + offB;
                else               g = Bl + offB;
            }
            cp16(dst, g);
        }
        asm volatile("cp.async.commit_group;");
    };

    wmma::fragment<wmma::accumulator, 16, 16, 16, float> acc[2][4];
    #pragma unroll
    for (int i = 0; i < 2; i++)
        #pragma unroll
        for (int j = 0; j < 4; j++)
            wmma::fill_fragment(acc[i][j], 0.0f);

    auto compute = [&](int st) {
        const h16* base = sm + st * STAGE;
        const h16* sAh_ = base;
        const h16* sAl_ = base + BUF;                 // valid iff TA==2
        const h16* sBh_ = base + TA * BUF;
        const h16* sBl_ = base + (TA + 1) * BUF;      // valid iff TB==2
        #pragma unroll
        for (int kk = 0; kk < 4; kk++) {
            const int ko = kk << 4;
            wmma::fragment<wmma::matrix_a, 16, 16, 16, h16, wmma::row_major> ah[2], al[2];
            #pragma unroll
            for (int i = 0; i < 2; i++) {
                wmma::load_matrix_sync(ah[i], sAh_ + (wm + (i << 4)) * PITCH + ko, PITCH);
                if (TA == 2)
                    wmma::load_matrix_sync(al[i], sAl_ + (wm + (i << 4)) * PITCH + ko, PITCH);
            }
            #pragma unroll
            for (int j = 0; j < 4; j++) {
                wmma::fragment<wmma::matrix_b, 16, 16, 16, h16, wmma::col_major> bf;
                wmma::load_matrix_sync(bf, sBh_ + (wn + (j << 4)) * PITCH + ko, PITCH);
                #pragma unroll
                for (int i = 0; i < 2; i++) {
                    wmma::mma_sync(acc[i][j], ah[i], bf, acc[i][j]);
                    if (TA == 2) wmma::mma_sync(acc[i][j], al[i], bf, acc[i][j]);
                }
                if (TB == 2) {
                    wmma::load_matrix_sync(bf, sBl_ + (wn + (j << 4)) * PITCH + ko, PITCH);
                    #pragma unroll
                    for (int i = 0; i < 2; i++)
                        wmma::mma_sync(acc[i][j], ah[i], bf, acc[i][j]);
                }
            }
        }
    };

    if (NSTAGE == 2) {
        load_stage(0, 0);
        for (int kt = 0; kt < nK; kt++) {
            if (kt + 1 < nK) {
                load_stage((kt + 1) & 1, kt + 1);
                asm volatile("cp.async.wait_group 1;");
            } else {
                asm volatile("cp.async.wait_group 0;");
            }
            __syncthreads();
            compute(kt & 1);
            __syncthreads();
        }
    } else {
        load_stage(0, 0);
        if (nK > 1) load_stage(1, 1);
        for (int kt = 0; kt < nK; kt++) {
            if (kt == nK - 1) asm volatile("cp.async.wait_group 0;");
            else              asm volatile("cp.async.wait_group 1;");
            __syncthreads();
            compute(kt % 3);
            __syncthreads();
            if (kt + 2 < nK) load_stage((kt + 2) % 3, kt + 2);
        }
    }

    if (!HOUT) {
        float* Cf = C + coff;
        #pragma unroll
        for (int i = 0; i < 2; i++)
            #pragma unroll
            for (int j = 0; j < 4; j++)
                wmma::store_matrix_sync(
                    &Cf[(long long)(m0 + wm + (i << 4)) * ldc + n0 + wn + (j << 4)],
                    acc[i][j], ldc, wmma::mem_row_major);
    } else {
        // stage fp32 acc in smem, emit coalesced fp16
        float* smf = (float*)sm;   // 128 x 132 floats = 67584 B <= stage smem
        #pragma unroll
        for (int i = 0; i < 2; i++)
            #pragma unroll
            for (int j = 0; j < 4; j++)
                wmma::store_matrix_sync(
                    &smf[(wm + (i << 4)) * 132 + wn + (j << 4)],
                    acc[i][j], 132, wmma::mem_row_major);
        __syncthreads();
        h16* Ch = (h16*)C + coff;
        #pragma unroll
        for (int it = 0; it < 64; it++) {
            int idx = tid + (it << 8);
            int m = idx >> 7, n = idx & 127;
            Ch[(long long)(m0 + m) * ldc + n0 + n] = __float2half_rn(smf[m * 132 + n]);
        }
    }
}

template <int TA, int TB, bool CSKIP, bool KLIM, bool HOUT>
static void rung(const h16* Ah, const h16* Al, const h16* Bh, const h16* Bl,
                 float* C, int M, int N, int K, int lda, int ldb, int ldc,
                 long long sA, long long sB, long long sC, int batch)
{
    constexpr int NBUF   = TA + TB;
    constexpr int NSTAGE = (NBUF == 4) ? 3 : 2;
    size_t smem = (size_t)NSTAGE * NBUF * 128 * 72 * sizeof(h16);
    if (HOUT && smem < 128 * 132 * sizeof(float)) smem = 128 * 132 * sizeof(float);
    cudaFuncSetAttribute(gemmH<TA, TB, CSKIP, KLIM, HOUT>,
                         cudaFuncAttributeMaxDynamicSharedMemorySize, (int)smem);
    dim3 grid(N / 128, M / 128, batch);
    gemmH<TA, TB, CSKIP, KLIM, HOUT><<<grid, 256, smem>>>(Ah, Al, Bh, Bl, C,
                                                          K, lda, ldb, ldc, sA, sB, sC);
}

// ---------------- split fp32 -> (fp16 hi, fp16 lo) ----------------------------
__global__ void split_kernel(const float4* __restrict__ src,
                             __half2* __restrict__ h,
                             __half2* __restrict__ l, int n4)
{
    int i = blockIdx.x * blockDim.x + threadIdx.x;
    if (i >= n4) return;
    float4 v = src[i];
    h16 h0 = __float2half_rn(v.x), h1 = __float2half_rn(v.y);
    h16 h2 = __float2half_rn(v.z), h3 = __float2half_rn(v.w);
    h16 l0 = __float2half_rn(v.x - __half2float(h0));
    h16 l1 = __float2half_rn(v.y - __half2float(h1));
    h16 l2 = __float2half_rn(v.z - __half2float(h2));
    h16 l3 = __float2half_rn(v.w - __half2float(h3));
    h[2*i]   = __halves2half2(h0, h1);
    h[2*i+1] = __halves2half2(h2, h3);
    l[2*i]   = __halves2half2(l0, l1);
    l[2*i+1] = __halves2half2(l2, l3);
}
static void split(const float* src, h16* h, h16* l, long long n)
{
    int n4 = (int)(n / 4);
    split_kernel<<<(n4 + 255) / 256, 256>>>((const float4*)src,
                                            (__half2*)h, (__half2*)l, n4);
}

// ---------------- transpose + split: src[R][C] fp32 -> dst[C][R] fp16 ----------
template <bool LO>
__global__ void tsplit_kernel(const float* __restrict__ src, int ld_src,
                              h16* __restrict__ dh, h16* __restrict__ dl,
                              int ld_dst, long long sSrc, long long sDst)
{
    __shared__ float t[32][33];
    const float* s = src + (long long)blockIdx.z * sSrc;
    h16* oh = dh + (long long)blockIdx.z * sDst;
    h16* ol = dl + (long long)blockIdx.z * sDst;
    int r0 = blockIdx.x * 32;
    int c0 = blockIdx.y * 32;
    int tx = threadIdx.x, ty = threadIdx.y;
    #pragma unroll
    for (int j = 0; j < 4; j++)
        t[ty + j * 8][tx] = s[(long long)(r0 + ty + j * 8) * ld_src + c0 + tx];
    __syncthreads();
    #pragma unroll
    for (int j = 0; j < 4; j++) {
        float v = t[tx][ty + j * 8];
        long long o = (long long)(c0 + ty + j * 8) * ld_dst + r0 + tx;
        h16 hi = __float2half_rn(v);
        oh[o] = hi;
        if (LO) ol[o] = __float2half_rn(v - __half2float(hi));
    }
}
template <bool LO>
static void tsplit(const float* src, int R, int Cc, int ld_src,
                   h16* dh, h16* dl, int ld_dst,
                   long long sSrc, long long sDst, int batch)
{
    dim3 grid(R / 32, Cc / 32, batch), block(32, 8);
    tsplit_kernel<LO><<<grid, block>>>(src, ld_src, dh, dl, ld_dst, sSrc, sDst);
}

// ---------------- rmsnorm (in-place, strided) -----------------------------------
__global__ void rmsnorm_kernel(float* __restrict__ x, const float* __restrict__ w,
                               int len, int stride)
{
    float* row = x + (long long)blockIdx.x * stride;
    __shared__ float red[256];
    int tid = threadIdx.x;
    float ss = 0.f;
    for (int j = tid; j < len; j += 256) { float v = row[j]; ss += v * v; }
    red[tid] = ss; __syncthreads();
    for (int s = 128; s > 0; s >>= 1) {
        if (tid < s) red[tid] += red[tid + s];
        __syncthreads();
    }
    float rr = rsqrtf(red[0] / (float)len + 1e-6f);
    for (int j = tid; j < len; j += 256) row[j] = row[j] * rr * w[j];
}

// ---------------- RoPE ----------------------------------------------------------
__global__ void rope_q_kernel(float* __restrict__ q)
{
    int idx = blockIdx.x * blockDim.x + threadIdx.x;
    if (idx >= SQ * NH * 32) return;
    int dp = idx & 31;
    int h  = (idx >> 5) & 127;
    int s  = idx >> 12;
    float a = (float)s * __expf(-(float)dp * (logf(10000.f) / 32.f));
    float c, sn;
    sincosf(a, &sn, &c);
    float* base = q + (long long)s * (NH * DQ) + h * DQ + DN;
    float x1 = base[dp], x2 = base[dp + 32];
    base[dp]      = x1 * c - x2 * sn;
    base[dp + 32] = x2 * c + x1 * sn;
}
__global__ void rope_kpe_kernel(const float* __restrict__ src0, int stride,
                                float* __restrict__ kpe)
{
    int idx = blockIdx.x * blockDim.x + threadIdx.x;
    if (idx >= SQ * 32) return;
    int dp = idx & 31;
    int s  = idx >> 5;
    float a = (float)s * __expf(-(float)dp * (logf(10000.f) / 32.f));
    float c, sn;
    sincosf(a, &sn, &c);
    const float* src = src0 + (long long)s * stride;
    float x1 = src[dp], x2 = src[dp + 32];
    kpe[s * DR + dp]      = x1 * c - x2 * sn;
    kpe[s * DR + dp + 32] = x2 * c + x1 * sn;
}

// ---------------- assemble K_full -> fp16 hi/lo ---------------------------------
__global__ void assemble_k_split_kernel(const float* __restrict__ kv,
                                        const float* __restrict__ kpe,
                                        h16* __restrict__ kh, h16* __restrict__ kl)
{
    long long idx = (long long)blockIdx.x * blockDim.x + threadIdx.x;
    if (idx >= (long long)NH * SQ * DQ) return;
    int d = (int)(idx % DQ);
    int j = (int)((idx / DQ) % SQ);
    int h = (int)(idx / ((long long)DQ * SQ));
    float v;
    if (d < DN) v = kv[(long long)j * (NH * 256) + h * 256 + d];
    else        v = kpe[j * DR + (d - DN)];
    h16 hi = __float2half_rn(v);
    kh[idx] = hi;
    kl[idx] = __float2half_rn(v - __half2float(hi));
}

// ---------------- causal softmax -> fp16 P (hi only, bounded writes) ------------
__global__ void softmax_p_kernel(const float* __restrict__ scores,
                                 h16* __restrict__ Ph)
{
    int r = blockIdx.x;                 // h*1024 + i
    int i = r & (SQ - 1);
    const float* row = scores + (long long)r * SQ;
    h16* ph = Ph + (long long)r * SQ;
    const float scale = 0.07216878365f; // 1/sqrt(192)
    const int jmax = ((i >> 7) + 1) << 7;  // PV reads k < this bound
    int tid = threadIdx.x;
    int lane = tid & 31, warp = tid >> 5;
    __shared__ float redm[8], reds[8];

    float v[4];
    #pragma unroll
    for (int t = 0; t < 4; t++) {
        int j = tid + t * 256;
        v[t] = (j <= i) ? row[j] * scale : -FLT_MAX;
    }
    float mx = fmaxf(fmaxf(v[0], v[1]), fmaxf(v[2], v[3]));
    #pragma unroll
    for (int o = 16; o > 0; o >>= 1) mx = fmaxf(mx, __shfl_xor_sync(~0u, mx, o));
    if (lane == 0) redm[warp] = mx;
    __syncthreads();
    mx = redm[0];
    #pragma unroll
    for (int w = 1; w < 8; w++) mx = fmaxf(mx, redm[w]);

    float e[4];
    float sum = 0.f;
    #pragma unroll
    for (int t = 0; t < 4; t++) {
        int j = tid + t * 256;
        e[t] = (j <= i) ? __expf(v[t] - mx) : 0.f;
        sum += e[t];
    }
    #pragma unroll
    for (int o = 16; o > 0; o >>= 1) sum += __shfl_xor_sync(~0u, sum, o);
    if (lane == 0) reds[warp] = sum;
    __syncthreads();
    sum = 0.f;
    #pragma unroll
    for (int w = 0; w < 8; w++) sum += reds[w];
    float inv = 1.f / sum;

    #pragma unroll
    for (int t = 0; t < 4; t++) {
        int j = tid + t * 256;
        if (j < jmax) ph[j] = __float2half_rn(e[t] * inv);
    }
}

// ---------------- host side -----------------------------------------------------
extern "C" void kernel_launch(void* const* d_in, const int* in_sizes, int n_in,
                              void* d_out, int out_size)
{
    const float* x     = (const float*)d_in[0];
    const float* Wqa   = (const float*)d_in[2];   // [7168,1536]
    const float* wqln  = (const float*)d_in[3];
    const float* Wqb   = (const float*)d_in[4];   // [1536,24576]
    const float* Wkva  = (const float*)d_in[5];   // [7168,576]
    const float* wkvln = (const float*)d_in[6];
    const float* Wkvb  = (const float*)d_in[7];   // [512,32768]
    const float* Wo    = (const float*)d_in[8];   // [16384,7168]
    float*       out   = (float*)d_out;

    float *qkva, *kpe, *q, *kv, *scores;
    cudaGetSymbolAddress((void**)&qkva,    g_qkva);
    cudaGetSymbolAddress((void**)&kpe,     g_kpe);
    cudaGetSymbolAddress((void**)&q,       g_q);
    cudaGetSymbolAddress((void**)&kv,      g_kv);
    cudaGetSymbolAddress((void**)&scores,  g_scores);

    h16 *xh,*xl,*qkvah,*qkval,*qh,*ql,*kh,*kl,*Phb,*aoh;
    h16 *Wdt_h,*Wdt_l,*Wqbt_h,*Wkvbt_h,*Wot_h,*Vt_h;
    cudaGetSymbolAddress((void**)&xh,    g_xh);    cudaGetSymbolAddress((void**)&xl,    g_xl);
    cudaGetSymbolAddress((void**)&qkvah, g_qkvah); cudaGetSymbolAddress((void**)&qkval, g_qkval);
    cudaGetSymbolAddress((void**)&qh,    g_qh);    cudaGetSymbolAddress((void**)&ql,    g_ql);
    cudaGetSymbolAddress((void**)&kh,    g_kh);    cudaGetSymbolAddress((void**)&kl,    g_kl);
    cudaGetSymbolAddress((void**)&Phb,   g_Ph);
    cudaGetSymbolAddress((void**)&aoh,   g_aoh);
    cudaGetSymbolAddress((void**)&Wdt_h, g_Wdt_h); cudaGetSymbolAddress((void**)&Wdt_l, g_Wdt_l);
    cudaGetSymbolAddress((void**)&Wqbt_h,  g_Wqb_t_h);
    cudaGetSymbolAddress((void**)&Wkvbt_h, g_Wkvb_t_h);
    cudaGetSymbolAddress((void**)&Wot_h,   g_Wo_t_h);
    cudaGetSymbolAddress((void**)&Vt_h,    g_Vt_h);

    // 0) split x; transpose(+split) weights into [N][K] K-major fp16
    split(x, xh, xl, (long long)SQ * HID);
    tsplit<true >(Wqa,  HID,    QLORA,    QLORA,    Wdt_h,                        Wdt_l,                        HID, 0, 0, 1);
    tsplit<true >(Wkva, HID,    576,      576,      Wdt_h + (long long)QLORA*HID, Wdt_l + (long long)QLORA*HID, HID, 0, 0, 1);
    tsplit<false>(Wqb,  QLORA,  NH * DQ,  NH * DQ,  Wqbt_h,  Wqbt_h, QLORA,  0, 0, 1);
    tsplit<false>(Wkvb, KVLORA, NH * 256, NH * 256, Wkvbt_h, Wkvbt_h,KVLORA, 0, 0, 1);
    tsplit<false>(Wo,   NH*DV,  HID,      HID,      Wot_h,   Wot_h,  NH*DV,  0, 0, 1);

    // 1) combined down-projection (3-term): [qa | kva] = x @ [Wqa | Wkva]
    rung<2,2,false,false,false>(xh, xl, Wdt_h, Wdt_l, qkva,
        SQ, DPN, HID, HID, HID, DPN, 0, 0, 0, 1);

    // 2) k_pe rope (pre-norm cols QLORA+512 .. +575) + rmsnorms (strided views)
    rope_kpe_kernel<<<(SQ * 32 + 255) / 256, 256>>>(qkva + QLORA + KVLORA, DPN, kpe);
    rmsnorm_kernel<<<SQ, 256>>>(qkva,         wqln,  QLORA,  DPN);
    rmsnorm_kernel<<<SQ, 256>>>(qkva + QLORA, wkvln, KVLORA, DPN);

    // 3) split combined activations; up-projections (2-term, occ2)
    split(qkva, qkvah, qkval, (long long)SQ * DPN);
    rung<2,1,false,false,false>(qkvah, qkval, Wqbt_h, Wqbt_h, q,
        SQ, NH * DQ, QLORA, DPN, QLORA, NH * DQ, 0, 0, 0, 1);
    rung<2,1,false,false,false>(qkvah + QLORA, qkval + QLORA, Wkvbt_h, Wkvbt_h, kv,
        SQ, NH * 256, KVLORA, DPN, KVLORA, NH * 256, 0, 0, 0, 1);

    // 4) RoPE on q; operand prep
    rope_q_kernel<<<(SQ * NH * 32 + 255) / 256, 256>>>(q);
    split(q, qh, ql, (long long)SQ * NH * DQ);
    assemble_k_split_kernel<<<(int)(((long long)NH * SQ * DQ + 255) / 256), 256>>>(kv, kpe, kh, kl);
    tsplit<false>(kv + DN, SQ, DV, NH * 256, Vt_h, Vt_h, SQ,
                  256, (long long)DV * SQ, NH);

    // 5) scores = Q @ K^T (3-term, causal tile-skip)
    rung<2,2,true,false,false>(qh, ql, kh, kl, scores,
        SQ, SQ, DQ, NH * DQ, DQ, SQ,
        DQ, (long long)SQ * DQ, (long long)SQ * SQ, NH);

    // 6) causal softmax -> fp16 P (hi only)
    softmax_p_kernel<<<NH * SQ, 256>>>(scores, Phb);

    // 7) out_h = P @ V  (pure fp16, k-limited, fp16 out -> aoh)
    rung<1,1,false,true,true>(Phb, Phb, Vt_h, Vt_h, (float*)aoh,
        SQ, DV, SQ, SQ, SQ, NH * DV,
        (long long)SQ * SQ, (long long)DV * SQ, DV, NH);

    // 8) output projection (pure fp16 inputs, occ2)
    rung<1,1,false,false,false>(aoh, aoh, Wot_h, Wot_h, out,
        SQ, HID, NH * DV, NH * DV, NH * DV, HID, 0, 0, 0, 1);
}

// round 10
// speedup vs baseline: 12.6451x; 1.2550x over previous
#include <cuda_runtime.h>
#include <cuda_fp16.h>
#include <mma.h>
#include <cfloat>
#include <cstdint>
#include <math.h>

using namespace nvcuda;
typedef __half h16;

#define SQ   1024
#define NH   128
#define DQ   192
#define DN   128
#define DR   64
#define DV   128
#define HID  7168
#define QLORA 1536
#define KVLORA 512
#define KVAP 640            // padded kv_a width (576 -> 640)
#define DPN  (QLORA + KVAP) // combined down-proj width = 2176 (17 * 128)

// ---------------- scratch (device globals; allocation-free rule) -------------
__device__ float g_qkva[SQ * DPN];        // [qa | kva] combined
__device__ float g_kpe[SQ * DR];
__device__ float g_q[SQ * NH * DQ];
__device__ float g_kv[SQ * NH * 256];

// fp16 activations
__device__ h16 g_xh[SQ * HID],  g_xl[SQ * HID];
__device__ h16 g_qkvah[SQ * DPN];
__device__ h16 g_qh[SQ * NH * DQ];
__device__ h16 g_kh[(long long)NH * SQ * DQ];
__device__ h16 g_Ph[(long long)NH * SQ * SQ];   // scores (unscaled) then P, in-place
__device__ h16 g_aoh[SQ * NH * DV];             // attn out, fp16

// fp16 transposed weights ([N][K] K-major), hi only
__device__ h16 g_Wdt_h[(long long)DPN * HID];   // [Wqa|Wkva]^T
__device__ h16 g_Wqb_t_h[NH * DQ * QLORA];
__device__ h16 g_Wkvb_t_h[NH * 256 * KVLORA];
__device__ h16 g_Wo_t_h[(long long)HID * NH * DV];
__device__ h16 g_Vt_h[(long long)NH * DV * SQ];

// ---------------- helpers -----------------------------------------------------
__device__ __forceinline__ void cp16(const h16* smem_dst, const h16* gsrc) {
    unsigned int saddr = (unsigned int)__cvta_generic_to_shared(smem_dst);
    asm volatile("cp.async.cg.shared.global [%0], [%1], 16;\n" :: "r"(saddr), "l"(gsrc));
}

// ---------------- mixed-term fp16 GEMM -----------------------------------------
// C[M,N] = A[M,K] @ B[N,K]^T  (K-major fp16; batch via blockIdx.z)
// Terms: Ah*Bh  (+ Al*Bh if TA==2)  (+ Ah*Bl if TB==2)
// HOUT: write fp16 (via smem staging) instead of fp32.
template <int TA, int TB, bool CSKIP, bool KLIM, bool HOUT>
__global__ void __launch_bounds__(256, (TA + TB == 4) ? 1 : 2)
gemmH(const h16* __restrict__ Ah, const h16* __restrict__ Al,
      const h16* __restrict__ Bh, const h16* __restrict__ Bl,
      float* __restrict__ C, int K, int lda, int ldb, int ldc,
      long long sA, long long sB, long long sC)
{
    constexpr int PITCH  = 72;           // 64 + 8 pad
    constexpr int BUF    = 128 * PITCH;
    constexpr int NBUF   = TA + TB;
    constexpr int NSTAGE = (NBUF == 4) ? 3 : 2;
    constexpr int STAGE  = NBUF * BUF;

    const int m0 = blockIdx.y << 7, n0 = blockIdx.x << 7;
    if (CSKIP && n0 >= m0 + 128) return;
    const int b = blockIdx.z;
    Ah += (long long)b * sA;
    if (TA == 2) Al += (long long)b * sA;
    Bh += (long long)b * sB;
    if (TB == 2) Bl += (long long)b * sB;
    const long long coff = (long long)b * sC;
    const int Kend = KLIM ? ((m0 + 128 < K) ? m0 + 128 : K) : K;
    const int nK = Kend >> 6;

    extern __shared__ h16 sm[];
    const int tid = threadIdx.x, wid = tid >> 5;
    const int wm = (wid & 3) << 5;
    const int wn = (wid >> 2) << 6;

    auto load_stage = [&](int st, int kc) {
        const int k0 = kc << 6;
        h16* base = sm + st * STAGE;
        #pragma unroll
        for (int i = 0; i < NBUF * 4; i++) {
            int c   = tid + (i << 8);
            int buf = c >> 10;
            int r   = (c >> 3) & 127;
            int k8  = (c & 7) << 3;
            h16* dst = base + buf * BUF + r * PITCH + k8;
            long long offA = (long long)(m0 + r) * lda + k0 + k8;
            long long offB = (long long)(n0 + r) * ldb + k0 + k8;
            const h16* g;
            if (TA == 2) {
                if      (buf == 0) g = Ah + offA;
                else if (buf == 1) g = Al + offA;
                else if (buf == 2) g = Bh + offB;
                else               g = Bl + offB;
            } else {
                if      (buf == 0) g = Ah + offA;
                else if (buf == 1) g = Bh + offB;
                else               g = Bl + offB;
            }
            cp16(dst, g);
        }
        asm volatile("cp.async.commit_group;");
    };

    wmma::fragment<wmma::accumulator, 16, 16, 16, float> acc[2][4];
    #pragma unroll
    for (int i = 0; i < 2; i++)
        #pragma unroll
        for (int j = 0; j < 4; j++)
            wmma::fill_fragment(acc[i][j], 0.0f);

    auto compute = [&](int st) {
        const h16* base = sm + st * STAGE;
        const h16* sAh_ = base;
        const h16* sAl_ = base + BUF;                 // valid iff TA==2
        const h16* sBh_ = base + TA * BUF;
        const h16* sBl_ = base + (TA + 1) * BUF;      // valid iff TB==2
        #pragma unroll
        for (int kk = 0; kk < 4; kk++) {
            const int ko = kk << 4;
            wmma::fragment<wmma::matrix_a, 16, 16, 16, h16, wmma::row_major> ah[2], al[2];
            #pragma unroll
            for (int i = 0; i < 2; i++) {
                wmma::load_matrix_sync(ah[i], sAh_ + (wm + (i << 4)) * PITCH + ko, PITCH);
                if (TA == 2)
                    wmma::load_matrix_sync(al[i], sAl_ + (wm + (i << 4)) * PITCH + ko, PITCH);
            }
            #pragma unroll
            for (int j = 0; j < 4; j++) {
                wmma::fragment<wmma::matrix_b, 16, 16, 16, h16, wmma::col_major> bf;
                wmma::load_matrix_sync(bf, sBh_ + (wn + (j << 4)) * PITCH + ko, PITCH);
                #pragma unroll
                for (int i = 0; i < 2; i++) {
                    wmma::mma_sync(acc[i][j], ah[i], bf, acc[i][j]);
                    if (TA == 2) wmma::mma_sync(acc[i][j], al[i], bf, acc[i][j]);
                }
                if (TB == 2) {
                    wmma::load_matrix_sync(bf, sBl_ + (wn + (j << 4)) * PITCH + ko, PITCH);
                    #pragma unroll
                    for (int i = 0; i < 2; i++)
                        wmma::mma_sync(acc[i][j], ah[i], bf, acc[i][j]);
                }
            }
        }
    };

    if (NSTAGE == 2) {
        load_stage(0, 0);
        for (int kt = 0; kt < nK; kt++) {
            if (kt + 1 < nK) {
                load_stage((kt + 1) & 1, kt + 1);
                asm volatile("cp.async.wait_group 1;");
            } else {
                asm volatile("cp.async.wait_group 0;");
            }
            __syncthreads();
            compute(kt & 1);
            __syncthreads();
        }
    } else {
        load_stage(0, 0);
        if (nK > 1) load_stage(1, 1);
        for (int kt = 0; kt < nK; kt++) {
            if (kt == nK - 1) asm volatile("cp.async.wait_group 0;");
            else              asm volatile("cp.async.wait_group 1;");
            __syncthreads();
            compute(kt % 3);
            __syncthreads();
            if (kt + 2 < nK) load_stage((kt + 2) % 3, kt + 2);
        }
    }

    if (!HOUT) {
        float* Cf = C + coff;
        #pragma unroll
        for (int i = 0; i < 2; i++)
            #pragma unroll
            for (int j = 0; j < 4; j++)
                wmma::store_matrix_sync(
                    &Cf[(long long)(m0 + wm + (i << 4)) * ldc + n0 + wn + (j << 4)],
                    acc[i][j], ldc, wmma::mem_row_major);
    } else {
        // stage fp32 acc in smem, emit coalesced fp16
        float* smf = (float*)sm;   // 128 x 132 floats = 67584 B <= stage smem
        #pragma unroll
        for (int i = 0; i < 2; i++)
            #pragma unroll
            for (int j = 0; j < 4; j++)
                wmma::store_matrix_sync(
                    &smf[(wm + (i << 4)) * 132 + wn + (j << 4)],
                    acc[i][j], 132, wmma::mem_row_major);
        __syncthreads();
        h16* Ch = (h16*)C + coff;
        #pragma unroll
        for (int it = 0; it < 64; it++) {
            int idx = tid + (it << 8);
            int m = idx >> 7, n = idx & 127;
            Ch[(long long)(m0 + m) * ldc + n0 + n] = __float2half_rn(smf[m * 132 + n]);
        }
    }
}

template <int TA, int TB, bool CSKIP, bool KLIM, bool HOUT>
static void rung(const h16* Ah, const h16* Al, const h16* Bh, const h16* Bl,
                 float* C, int M, int N, int K, int lda, int ldb, int ldc,
                 long long sA, long long sB, long long sC, int batch)
{
    constexpr int NBUF   = TA + TB;
    constexpr int NSTAGE = (NBUF == 4) ? 3 : 2;
    size_t smem = (size_t)NSTAGE * NBUF * 128 * 72 * sizeof(h16);
    if (HOUT && smem < 128 * 132 * sizeof(float)) smem = 128 * 132 * sizeof(float);
    cudaFuncSetAttribute(gemmH<TA, TB, CSKIP, KLIM, HOUT>,
                         cudaFuncAttributeMaxDynamicSharedMemorySize, (int)smem);
    dim3 grid(N / 128, M / 128, batch);
    gemmH<TA, TB, CSKIP, KLIM, HOUT><<<grid, 256, smem>>>(Ah, Al, Bh, Bl, C,
                                                          K, lda, ldb, ldc, sA, sB, sC);
}

// ---------------- split fp32 -> fp16 hi (+ optional lo) ------------------------
template <bool LO>
__global__ void split_kernel(const float4* __restrict__ src,
                             __half2* __restrict__ h,
                             __half2* __restrict__ l, int n4)
{
    int i = blockIdx.x * blockDim.x + threadIdx.x;
    if (i >= n4) return;
    float4 v = src[i];
    h16 h0 = __float2half_rn(v.x), h1 = __float2half_rn(v.y);
    h16 h2 = __float2half_rn(v.z), h3 = __float2half_rn(v.w);
    h[2*i]   = __halves2half2(h0, h1);
    h[2*i+1] = __halves2half2(h2, h3);
    if (LO) {
        h16 l0 = __float2half_rn(v.x - __half2float(h0));
        h16 l1 = __float2half_rn(v.y - __half2float(h1));
        h16 l2 = __float2half_rn(v.z - __half2float(h2));
        h16 l3 = __float2half_rn(v.w - __half2float(h3));
        l[2*i]   = __halves2half2(l0, l1);
        l[2*i+1] = __halves2half2(l2, l3);
    }
}
template <bool LO>
static void split(const float* src, h16* h, h16* l, long long n)
{
    int n4 = (int)(n / 4);
    split_kernel<LO><<<(n4 + 255) / 256, 256>>>((const float4*)src,
                                                (__half2*)h, (__half2*)l, n4);
}

// ---------------- transpose + convert: src[R][C] fp32 -> dst[C][R] fp16 --------
__global__ void tconv_kernel(const float* __restrict__ src, int ld_src,
                             h16* __restrict__ dh,
                             int ld_dst, long long sSrc, long long sDst)
{
    __shared__ float t[32][33];
    const float* s = src + (long long)blockIdx.z * sSrc;
    h16* oh = dh + (long long)blockIdx.z * sDst;
    int r0 = blockIdx.x * 32;
    int c0 = blockIdx.y * 32;
    int tx = threadIdx.x, ty = threadIdx.y;
    #pragma unroll
    for (int j = 0; j < 4; j++)
        t[ty + j * 8][tx] = s[(long long)(r0 + ty + j * 8) * ld_src + c0 + tx];
    __syncthreads();
    #pragma unroll
    for (int j = 0; j < 4; j++) {
        float v = t[tx][ty + j * 8];
        long long o = (long long)(c0 + ty + j * 8) * ld_dst + r0 + tx;
        oh[o] = __float2half_rn(v);
    }
}
static void tconv(const float* src, int R, int Cc, int ld_src,
                  h16* dh, int ld_dst, long long sSrc, long long sDst, int batch)
{
    dim3 grid(R / 32, Cc / 32, batch), block(32, 8);
    tconv_kernel<<<grid, block>>>(src, ld_src, dh, ld_dst, sSrc, sDst);
}

// ---------------- rmsnorm (in-place, strided) -----------------------------------
__global__ void rmsnorm_kernel(float* __restrict__ x, const float* __restrict__ w,
                               int len, int stride)
{
    float* row = x + (long long)blockIdx.x * stride;
    __shared__ float red[256];
    int tid = threadIdx.x;
    float ss = 0.f;
    for (int j = tid; j < len; j += 256) { float v = row[j]; ss += v * v; }
    red[tid] = ss; __syncthreads();
    for (int s = 128; s > 0; s >>= 1) {
        if (tid < s) red[tid] += red[tid + s];
        __syncthreads();
    }
    float rr = rsqrtf(red[0] / (float)len + 1e-6f);
    for (int j = tid; j < len; j += 256) row[j] = row[j] * rr * w[j];
}

// ---------------- RoPE ----------------------------------------------------------
__global__ void rope_q_kernel(float* __restrict__ q)
{
    int idx = blockIdx.x * blockDim.x + threadIdx.x;
    if (idx >= SQ * NH * 32) return;
    int dp = idx & 31;
    int h  = (idx >> 5) & 127;
    int s  = idx >> 12;
    float a = (float)s * __expf(-(float)dp * (logf(10000.f) / 32.f));
    float c, sn;
    sincosf(a, &sn, &c);
    float* base = q + (long long)s * (NH * DQ) + h * DQ + DN;
    float x1 = base[dp], x2 = base[dp + 32];
    base[dp]      = x1 * c - x2 * sn;
    base[dp + 32] = x2 * c + x1 * sn;
}
__global__ void rope_kpe_kernel(const float* __restrict__ src0, int stride,
                                float* __restrict__ kpe)
{
    int idx = blockIdx.x * blockDim.x + threadIdx.x;
    if (idx >= SQ * 32) return;
    int dp = idx & 31;
    int s  = idx >> 5;
    float a = (float)s * __expf(-(float)dp * (logf(10000.f) / 32.f));
    float c, sn;
    sincosf(a, &sn, &c);
    const float* src = src0 + (long long)s * stride;
    float x1 = src[dp], x2 = src[dp + 32];
    kpe[s * DR + dp]      = x1 * c - x2 * sn;
    kpe[s * DR + dp + 32] = x2 * c + x1 * sn;
}

// ---------------- assemble K_full -> fp16 (hi only) ----------------------------
__global__ void assemble_k_kernel(const float* __restrict__ kv,
                                  const float* __restrict__ kpe,
                                  h16* __restrict__ kh)
{
    long long idx = (long long)blockIdx.x * blockDim.x + threadIdx.x;
    if (idx >= (long long)NH * SQ * DQ) return;
    int d = (int)(idx % DQ);
    int j = (int)((idx / DQ) % SQ);
    int h = (int)(idx / ((long long)DQ * SQ));
    float v;
    if (d < DN) v = kv[(long long)j * (NH * 256) + h * 256 + d];
    else        v = kpe[j * DR + (d - DN)];
    kh[idx] = __float2half_rn(v);
}

// ---------------- causal softmax, fp16 in-place (scores -> P) ------------------
__global__ void softmax_p_kernel(h16* __restrict__ S)
{
    int r = blockIdx.x;                 // h*1024 + i
    int i = r & (SQ - 1);
    h16* row = S + (long long)r * SQ;
    const float scale = 0.07216878365f; // 1/sqrt(192)
    const int jmax = ((i >> 7) + 1) << 7;  // PV reads k < this bound
    int tid = threadIdx.x;
    int lane = tid & 31, warp = tid >> 5;
    __shared__ float redm[8], reds[8];

    float v[4];
    #pragma unroll
    for (int t = 0; t < 4; t++) {
        int j = tid + t * 256;
        v[t] = (j <= i) ? __half2float(row[j]) * scale : -FLT_MAX;
    }
    float mx = fmaxf(fmaxf(v[0], v[1]), fmaxf(v[2], v[3]));
    #pragma unroll
    for (int o = 16; o > 0; o >>= 1) mx = fmaxf(mx, __shfl_xor_sync(~0u, mx, o));
    if (lane == 0) redm[warp] = mx;
    __syncthreads();
    mx = redm[0];
    #pragma unroll
    for (int w = 1; w < 8; w++) mx = fmaxf(mx, redm[w]);

    float e[4];
    float sum = 0.f;
    #pragma unroll
    for (int t = 0; t < 4; t++) {
        int j = tid + t * 256;
        e[t] = (j <= i) ? __expf(v[t] - mx) : 0.f;
        sum += e[t];
    }
    #pragma unroll
    for (int o = 16; o > 0; o >>= 1) sum += __shfl_xor_sync(~0u, sum, o);
    if (lane == 0) reds[warp] = sum;
    __syncthreads();
    sum = 0.f;
    #pragma unroll
    for (int w = 0; w < 8; w++) sum += reds[w];
    float inv = 1.f / sum;

    #pragma unroll
    for (int t = 0; t < 4; t++) {
        int j = tid + t * 256;
        if (j < jmax) row[j] = __float2half_rn(e[t] * inv);
    }
}

// ---------------- host side -----------------------------------------------------
extern "C" void kernel_launch(void* const* d_in, const int* in_sizes, int n_in,
                              void* d_out, int out_size)
{
    const float* x     = (const float*)d_in[0];
    const float* Wqa   = (const float*)d_in[2];   // [7168,1536]
    const float* wqln  = (const float*)d_in[3];
    const float* Wqb   = (const float*)d_in[4];   // [1536,24576]
    const float* Wkva  = (const float*)d_in[5];   // [7168,576]
    const float* wkvln = (const float*)d_in[6];
    const float* Wkvb  = (const float*)d_in[7];   // [512,32768]
    const float* Wo    = (const float*)d_in[8];   // [16384,7168]
    float*       out   = (float*)d_out;

    float *qkva, *kpe, *q, *kv;
    cudaGetSymbolAddress((void**)&qkva, g_qkva);
    cudaGetSymbolAddress((void**)&kpe,  g_kpe);
    cudaGetSymbolAddress((void**)&q,    g_q);
    cudaGetSymbolAddress((void**)&kv,   g_kv);

    h16 *xh,*xl,*qkvah,*qh,*kh,*Phb,*aoh;
    h16 *Wdt_h,*Wqbt_h,*Wkvbt_h,*Wot_h,*Vt_h;
    cudaGetSymbolAddress((void**)&xh,    g_xh);    cudaGetSymbolAddress((void**)&xl,    g_xl);
    cudaGetSymbolAddress((void**)&qkvah, g_qkvah);
    cudaGetSymbolAddress((void**)&qh,    g_qh);
    cudaGetSymbolAddress((void**)&kh,    g_kh);
    cudaGetSymbolAddress((void**)&Phb,   g_Ph);
    cudaGetSymbolAddress((void**)&aoh,   g_aoh);
    cudaGetSymbolAddress((void**)&Wdt_h, g_Wdt_h);
    cudaGetSymbolAddress((void**)&Wqbt_h,  g_Wqb_t_h);
    cudaGetSymbolAddress((void**)&Wkvbt_h, g_Wkvb_t_h);
    cudaGetSymbolAddress((void**)&Wot_h,   g_Wo_t_h);
    cudaGetSymbolAddress((void**)&Vt_h,    g_Vt_h);

    // 0) split x (hi+lo); transpose+convert weights into [N][K] K-major fp16 (hi)
    split<true>(x, xh, xl, (long long)SQ * HID);
    tconv(Wqa,  HID,    QLORA,    QLORA,    Wdt_h,                        HID,    0, 0, 1);
    tconv(Wkva, HID,    576,      576,      Wdt_h + (long long)QLORA*HID, HID,    0, 0, 1);
    tconv(Wqb,  QLORA,  NH * DQ,  NH * DQ,  Wqbt_h,  QLORA,  0, 0, 1);
    tconv(Wkvb, KVLORA, NH * 256, NH * 256, Wkvbt_h, KVLORA, 0, 0, 1);
    tconv(Wo,   NH*DV,  HID,      HID,      Wot_h,   NH*DV,  0, 0, 1);

    // 1) combined down-projection (2,1): [qa | kva] = x @ [Wqa | Wkva]
    rung<2,1,false,false,false>(xh, xl, Wdt_h, Wdt_h, qkva,
        SQ, DPN, HID, HID, HID, DPN, 0, 0, 0, 1);

    // 2) k_pe rope (pre-norm cols QLORA+512 .. +575) + rmsnorms (strided views)
    rope_kpe_kernel<<<(SQ * 32 + 255) / 256, 256>>>(qkva + QLORA + KVLORA, DPN, kpe);
    rmsnorm_kernel<<<SQ, 256>>>(qkva,         wqln,  QLORA,  DPN);
    rmsnorm_kernel<<<SQ, 256>>>(qkva + QLORA, wkvln, KVLORA, DPN);

    // 3) convert activations (hi only); up-projections (1,1), occ2
    split<false>(qkva, qkvah, qkvah, (long long)SQ * DPN);
    rung<1,1,false,false,false>(qkvah, qkvah, Wqbt_h, Wqbt_h, q,
        SQ, NH * DQ, QLORA, DPN, QLORA, NH * DQ, 0, 0, 0, 1);
    rung<1,1,false,false,false>(qkvah + QLORA, qkvah + QLORA, Wkvbt_h, Wkvbt_h, kv,
        SQ, NH * 256, KVLORA, DPN, KVLORA, NH * 256, 0, 0, 0, 1);

    // 4) RoPE on q; operand prep (hi only)
    rope_q_kernel<<<(SQ * NH * 32 + 255) / 256, 256>>>(q);
    split<false>(q, qh, qh, (long long)SQ * NH * DQ);
    assemble_k_kernel<<<(int)(((long long)NH * SQ * DQ + 255) / 256), 256>>>(kv, kpe, kh);
    tconv(kv + DN, SQ, DV, NH * 256, Vt_h, SQ, 256, (long long)DV * SQ, NH);

    // 5) scores = Q @ K^T (1,1), causal tile-skip, fp16 out directly into P buffer
    rung<1,1,true,false,true>(qh, qh, kh, kh, (float*)Phb,
        SQ, SQ, DQ, NH * DQ, DQ, SQ,
        DQ, (long long)SQ * DQ, (long long)SQ * SQ, NH);

    // 6) causal softmax, fp16 in-place (scores -> P)
    softmax_p_kernel<<<NH * SQ, 256>>>(Phb);

    // 7) out_h = P @ V (1,1), k-limited, fp16 out -> aoh
    rung<1,1,false,true,true>(Phb, Phb, Vt_h, Vt_h, (float*)aoh,
        SQ, DV, SQ, SQ, SQ, NH * DV,
        (long long)SQ * SQ, (long long)DV * SQ, DV, NH);

    // 8) output projection (1,1), occ2
    rung<1,1,false,false,false>(aoh, aoh, Wot_h, Wot_h, out,
        SQ, HID, NH * DV, NH * DV, NH * DV, HID, 0, 0, 0, 1);
}